// round 1
// baseline (speedup 1.0000x reference)
#include <cuda_runtime.h>
#include <stdint.h>
#include <math.h>

// Problem constants (fixed shapes for this problem instance)
#define KD    512          // key dims = T*C
#define LP    16           // prompt length
#define EMB   512          // embedding dims
#define TOPK  4
#define ROW_ELEMS (LP*EMB) // 8192 floats per prompt row

// GEMM tiling
#define BM 128
#define BN 128
#define BK 16

// Scratch (device globals; no runtime allocation allowed)
__device__ float g_scores[4096ull * 4096ull];  // 64 MB
__device__ float g_invk[4096];
__device__ int   g_topidx[4096 * TOPK];

// ---------------- packed f32x2 helpers ----------------
__device__ __forceinline__ unsigned long long pack2(float lo, float hi) {
    unsigned long long r;
    asm("mov.b64 %0, {%1,%2};" : "=l"(r) : "f"(lo), "f"(hi));
    return r;
}
__device__ __forceinline__ void unpack2(unsigned long long v, float& lo, float& hi) {
    asm("mov.b64 {%0,%1}, %2;" : "=f"(lo), "=f"(hi) : "l"(v));
}
__device__ __forceinline__ void fma2(unsigned long long& d, unsigned long long a, unsigned long long b) {
    asm("fma.rn.f32x2 %0, %1, %2, %0;" : "+l"(d) : "l"(a), "l"(b));
}

// ---------------- kernel 1: per-key inverse L2 norm ----------------
__global__ void key_norm_kernel(const float* __restrict__ keys, int P) {
    int row = blockIdx.x * blockDim.y + threadIdx.y;
    if (row >= P) return;
    const float* kr = keys + (size_t)row * KD;
    float s = 0.f;
    for (int i = threadIdx.x; i < KD; i += 32) {
        float v = kr[i];
        s = fmaf(v, v, s);
    }
    #pragma unroll
    for (int o = 16; o; o >>= 1) s += __shfl_xor_sync(0xffffffffu, s, o);
    if (threadIdx.x == 0) {
        double d = (double)fmaxf(s, 1e-12f);
        g_invk[row] = (float)(1.0 / sqrt(d));
    }
}

// ---------------- kernel 2: fp32 NT GEMM (scores = X * K^T, col-scaled by invk) ----------------
__device__ __forceinline__ void load_tiles(
    float (&As)[2][BK][BM + 4], float (&Bs)[2][BK][BN + 4],
    const float* __restrict__ X, const float* __restrict__ Kk,
    int rowbase, int colbase, int k0, int st, int t)
{
    #pragma unroll
    for (int i = 0; i < 2; i++) {
        int idx = t + i * 256;
        int r  = idx >> 2;
        int c4 = idx & 3;
        const float4 va = *(const float4*)(X + (size_t)(rowbase + r) * KD + k0 + c4 * 4);
        As[st][c4 * 4 + 0][r] = va.x;
        As[st][c4 * 4 + 1][r] = va.y;
        As[st][c4 * 4 + 2][r] = va.z;
        As[st][c4 * 4 + 3][r] = va.w;
        const float4 vb = *(const float4*)(Kk + (size_t)(colbase + r) * KD + k0 + c4 * 4);
        Bs[st][c4 * 4 + 0][r] = vb.x;
        Bs[st][c4 * 4 + 1][r] = vb.y;
        Bs[st][c4 * 4 + 2][r] = vb.z;
        Bs[st][c4 * 4 + 3][r] = vb.w;
    }
}

__global__ __launch_bounds__(256, 2)
void score_gemm(const float* __restrict__ X, const float* __restrict__ Kk, int P) {
    __shared__ float As[2][BK][BM + 4];
    __shared__ float Bs[2][BK][BN + 4];

    const int t  = threadIdx.x;           // 0..255
    const int tx = t & 15;                 // N direction
    const int ty = t >> 4;                 // M direction
    const int rowbase = blockIdx.y * BM;
    const int colbase = blockIdx.x * BN;

    // acc[mp][n]: mp = M-pair (rows ty*8+2mp, ty*8+2mp+1), n = 0..7 cols
    unsigned long long acc[4][8];
    #pragma unroll
    for (int mp = 0; mp < 4; mp++)
        #pragma unroll
        for (int n = 0; n < 8; n++)
            acc[mp][n] = 0ull;

    load_tiles(As, Bs, X, Kk, rowbase, colbase, 0, 0, t);
    __syncthreads();

    const int NK = KD / BK;   // 32
    for (int kb = 0; kb < NK; kb++) {
        const int st = kb & 1;
        if (kb + 1 < NK)
            load_tiles(As, Bs, X, Kk, rowbase, colbase, (kb + 1) * BK, st ^ 1, t);

        #pragma unroll
        for (int kk = 0; kk < BK; kk++) {
            // A fragment: 8 consecutive M values -> 4 f32x2 pairs, directly as u64 pairs
            const ulonglong2 a01 = *(const ulonglong2*)&As[st][kk][ty * 8];
            const ulonglong2 a23 = *(const ulonglong2*)&As[st][kk][ty * 8 + 4];
            unsigned long long ap[4] = {a01.x, a01.y, a23.x, a23.y};
            // B fragment: 8 scalar N values
            const float4 b0 = *(const float4*)&Bs[st][kk][tx * 8];
            const float4 b1 = *(const float4*)&Bs[st][kk][tx * 8 + 4];
            const float bv[8] = {b0.x, b0.y, b0.z, b0.w, b1.x, b1.y, b1.z, b1.w};
            #pragma unroll
            for (int n = 0; n < 8; n++) {
                const unsigned long long bd = pack2(bv[n], bv[n]);
                #pragma unroll
                for (int mp = 0; mp < 4; mp++)
                    fma2(acc[mp][n], ap[mp], bd);
            }
        }
        __syncthreads();
    }

    // epilogue: scale columns by per-key inverse norm, store
    float inv[8];
    #pragma unroll
    for (int n = 0; n < 8; n++) inv[n] = g_invk[colbase + tx * 8 + n];

    #pragma unroll
    for (int mp = 0; mp < 4; mp++) {
        const int r0 = rowbase + ty * 8 + mp * 2;
        float lo[8], hi[8];
        #pragma unroll
        for (int n = 0; n < 8; n++) {
            float a, b;
            unpack2(acc[mp][n], a, b);
            lo[n] = a * inv[n];
            hi[n] = b * inv[n];
        }
        float* p0 = g_scores + (size_t)r0 * P + colbase + tx * 8;
        float* p1 = p0 + P;
        *(float4*)(p0 + 0) = make_float4(lo[0], lo[1], lo[2], lo[3]);
        *(float4*)(p0 + 4) = make_float4(lo[4], lo[5], lo[6], lo[7]);
        *(float4*)(p1 + 0) = make_float4(hi[0], hi[1], hi[2], hi[3]);
        *(float4*)(p1 + 4) = make_float4(hi[4], hi[5], hi[6], hi[7]);
    }
}

// ---------------- kernel 3: top-4 smallest scores per row ----------------
// scores = cos * (positive row scale); reference takes top_k of -cos, i.e. the
// 4 SMALLEST cos values, ordered ascending, ties -> lower index first.
__device__ __forceinline__ void merge4(unsigned long long a[4], const unsigned long long b[4]) {
    unsigned long long r[4];
    int i = 0, j = 0;
    #pragma unroll
    for (int q = 0; q < 4; q++) {
        bool takeA = (j >= 4) || (i < 4 && a[i] <= b[j]);
        r[q] = takeA ? a[i] : b[j];
        if (takeA) i++; else j++;
    }
    #pragma unroll
    for (int q = 0; q < 4; q++) a[q] = r[q];
}

__global__ void topk_kernel(int P) {
    const int row = blockIdx.x;
    const float* s = g_scores + (size_t)row * P;

    unsigned long long best[4] = {~0ull, ~0ull, ~0ull, ~0ull};
    for (int i = threadIdx.x; i < P; i += blockDim.x) {
        float v = s[i];
        unsigned u = __float_as_uint(v);
        u = (u & 0x80000000u) ? ~u : (u | 0x80000000u);  // order-preserving map
        unsigned long long key = ((unsigned long long)u << 32) | (unsigned)i;
        if (key < best[3]) {
            best[3] = key;
            #pragma unroll
            for (int q = 3; q > 0; q--)
                if (best[q] < best[q - 1]) {
                    unsigned long long tmp = best[q];
                    best[q] = best[q - 1];
                    best[q - 1] = tmp;
                }
        }
    }

    // warp butterfly merge
    #pragma unroll
    for (int off = 16; off; off >>= 1) {
        unsigned long long oth[4];
        #pragma unroll
        for (int q = 0; q < 4; q++)
            oth[q] = __shfl_xor_sync(0xffffffffu, best[q], off);
        merge4(best, oth);
    }

    __shared__ unsigned long long sm[4][4];
    const int wid = threadIdx.x >> 5;
    const int lane = threadIdx.x & 31;
    if (lane == 0) {
        #pragma unroll
        for (int q = 0; q < 4; q++) sm[wid][q] = best[q];
    }
    __syncthreads();

    if (threadIdx.x == 0) {
        unsigned long long fin[4];
        #pragma unroll
        for (int q = 0; q < 4; q++) fin[q] = sm[0][q];
        const int nw = blockDim.x >> 5;
        for (int w = 1; w < nw; w++) {
            unsigned long long o[4];
            #pragma unroll
            for (int q = 0; q < 4; q++) o[q] = sm[w][q];
            merge4(fin, o);
        }
        #pragma unroll
        for (int q = 0; q < 4; q++)
            g_topidx[row * TOPK + q] = (int)(fin[q] & 0xffffffffu);
    }
}

// ---------------- kernel 4: gather prompt rows ----------------
__global__ void gather_kernel(const float* __restrict__ pv, float* __restrict__ out) {
    const int b = blockIdx.x;
    const int j = blockIdx.y;
    const int idx = g_topidx[b * TOPK + j];
    const float4* src = (const float4*)(pv + (size_t)idx * ROW_ELEMS);
    float4* dst = (float4*)(out + (size_t)b * (TOPK * ROW_ELEMS) + (size_t)j * ROW_ELEMS);
    #pragma unroll 4
    for (int i = threadIdx.x; i < ROW_ELEMS / 4; i += blockDim.x)
        dst[i] = src[i];
}

// ---------------- launcher ----------------
extern "C" void kernel_launch(void* const* d_in, const int* in_sizes, int n_in,
                              void* d_out, int out_size) {
    const float* x    = (const float*)d_in[0];   // (B, T, C) contiguous == (B, 512)
    const float* keys = (const float*)d_in[1];   // (P, 512)
    const float* pv   = (const float*)d_in[2];   // (P, 16, 512)
    float* out = (float*)d_out;                  // (B, 64, 512)

    const int B = in_sizes[0] / KD;   // 4096
    const int P = in_sizes[1] / KD;   // 4096

    key_norm_kernel<<<(P + 7) / 8, dim3(32, 8)>>>(keys, P);
    score_gemm<<<dim3(P / BN, B / BM), 256>>>(x, keys, P);
    topk_kernel<<<B, 128>>>(P);
    gather_kernel<<<dim3(B, TOPK), 256>>>(pv, out);
}

// round 4
// speedup vs baseline: 1.5217x; 1.5217x over previous
#include <cuda_runtime.h>
#include <cuda_bf16.h>
#include <stdint.h>
#include <math.h>

// ---------------- problem constants ----------------
#define KD    512
#define TOPK  4
#define ROW_ELEMS 8192
#define NB 4096
#define NP 4096
#define CAND 16

// ---------------- GEMM tiling ----------------
#define BM 128
#define BN 128
#define BK 32
#define STAGES 3
#define NKT (KD/BK)          // 16 k-steps
#define A_STAGE_BYTES (BM*BK*2)   // 8192
#define B_STAGE_BYTES (BN*BK*2)   // 8192

// ---------------- device scratch ----------------
__device__ float g_scores[(size_t)NB * NP];          // 64 MB
__device__ float g_invk[NP];
__device__ int   g_cand[NB * CAND];
__device__ int   g_topidx[NB * TOPK];
__device__ __nv_bfloat16 g_Xb[(size_t)NB * KD];      // 4 MB
__device__ __nv_bfloat16 g_Kb[(size_t)NP * KD];      // 4 MB (pre-scaled by invk)

// ---------------- helpers ----------------
__device__ __forceinline__ uint32_t smem_to_u32(const void* p) {
    uint32_t a;
    asm("{ .reg .u64 t; cvta.to.shared.u64 t, %1; cvt.u32.u64 %0, t; }" : "=r"(a) : "l"(p));
    return a;
}
__device__ __forceinline__ void cp16(uint32_t dst, const void* src) {
    asm volatile("cp.async.cg.shared.global [%0], [%1], 16;" :: "r"(dst), "l"(src) : "memory");
}
#define CP_COMMIT() asm volatile("cp.async.commit_group;" ::: "memory")
#define CP_WAIT1()  asm volatile("cp.async.wait_group 1;" ::: "memory")

__device__ __forceinline__ void ldm4(uint32_t* r, uint32_t a) {
    asm volatile("ldmatrix.sync.aligned.m8n8.x4.shared.b16 {%0,%1,%2,%3}, [%4];"
                 : "=r"(r[0]), "=r"(r[1]), "=r"(r[2]), "=r"(r[3]) : "r"(a));
}
__device__ __forceinline__ void mma16816(float* c, const uint32_t* a, uint32_t b0, uint32_t b1) {
    asm volatile("mma.sync.aligned.m16n8k16.row.col.f32.bf16.bf16.f32 "
                 "{%0,%1,%2,%3}, {%4,%5,%6,%7}, {%8,%9}, {%0,%1,%2,%3};"
                 : "+f"(c[0]), "+f"(c[1]), "+f"(c[2]), "+f"(c[3])
                 : "r"(a[0]), "r"(a[1]), "r"(a[2]), "r"(a[3]), "r"(b0), "r"(b1));
}

// ---------------- kernel 1: per-key inverse L2 norm ----------------
__global__ void key_norm_kernel(const float* __restrict__ keys) {
    int row = blockIdx.x * blockDim.y + threadIdx.y;
    const float* kr = keys + (size_t)row * KD;
    float s = 0.f;
    for (int i = threadIdx.x; i < KD; i += 32) { float v = kr[i]; s = fmaf(v, v, s); }
    #pragma unroll
    for (int o = 16; o; o >>= 1) s += __shfl_xor_sync(0xffffffffu, s, o);
    if (threadIdx.x == 0) {
        double d = (double)fmaxf(s, 1e-12f);
        g_invk[row] = (float)(1.0 / sqrt(d));
    }
}

// ---------------- kernel 2: fp32 -> bf16 convert (row-major) ----------------
__device__ __forceinline__ unsigned pack_bf16(float a, float b) {
    __nv_bfloat16 ha = __float2bfloat16_rn(a);
    __nv_bfloat16 hb = __float2bfloat16_rn(b);
    unsigned short ua = *(unsigned short*)&ha;
    unsigned short ub = *(unsigned short*)&hb;
    return (unsigned)ua | ((unsigned)ub << 16);
}
__global__ void convert_kernel(const float* __restrict__ src, int which) {
    int i = blockIdx.x * blockDim.x + threadIdx.x;   // one 8-elem chunk each
    const float* s = src + (size_t)i * 8;
    float4 f0 = *(const float4*)s;
    float4 f1 = *(const float4*)(s + 4);
    if (which) {
        float iv = g_invk[i >> 6];                    // row = i*8/512
        f0.x *= iv; f0.y *= iv; f0.z *= iv; f0.w *= iv;
        f1.x *= iv; f1.y *= iv; f1.z *= iv; f1.w *= iv;
    }
    uint4 o;
    o.x = pack_bf16(f0.x, f0.y); o.y = pack_bf16(f0.z, f0.w);
    o.z = pack_bf16(f1.x, f1.y); o.w = pack_bf16(f1.z, f1.w);
    uint4* dst = which ? (uint4*)g_Kb : (uint4*)g_Xb;
    dst[i] = o;
}

// ---------------- kernel 3: coarse bf16 HMMA GEMM ----------------
// smem layout per stage: [128 rows][4 chunks of 16B], phys chunk = c ^ ((row>>1)&3)
__global__ void __launch_bounds__(256) coarse_gemm() {
    __shared__ __align__(1024) char sA[STAGES][A_STAGE_BYTES];
    __shared__ __align__(1024) char sB[STAGES][B_STAGE_BYTES];
    const uint32_t aU = smem_to_u32(sA);
    const uint32_t bU = smem_to_u32(sB);
    const int t = threadIdx.x;
    const int rowbase = blockIdx.y * BM;
    const int colbase = blockIdx.x * BN;
    const __nv_bfloat16* Xb = g_Xb;
    const __nv_bfloat16* Kb = g_Kb;

    // --- async load of one k-step tile pair into stage st ---
    auto load_stage = [&](int st, int kt) {
        const int k0 = kt * BK;
        #pragma unroll
        for (int i = 0; i < 2; i++) {
            int ch = t + i * 256;
            int row = ch >> 2, c = ch & 3;
            int ph = c ^ ((row >> 1) & 3);
            cp16(aU + st * A_STAGE_BYTES + row * 64 + ph * 16,
                 Xb + (size_t)(rowbase + row) * KD + k0 + c * 8);
        }
        #pragma unroll
        for (int i = 0; i < 2; i++) {
            int ch = t + i * 256;
            int row = ch >> 2, c = ch & 3;
            int ph = c ^ ((row >> 1) & 3);
            cp16(bU + st * B_STAGE_BYTES + row * 64 + ph * 16,
                 Kb + (size_t)(colbase + row) * KD + k0 + c * 8);
        }
    };

    load_stage(0, 0); CP_COMMIT();
    load_stage(1, 1); CP_COMMIT();

    const int wid = t >> 5, lane = t & 31;
    const int wm = wid & 3, wn = wid >> 2;   // 4x2 warp grid: 32-row x 64-col tiles

    float acc[2][8][4];
    #pragma unroll
    for (int mt = 0; mt < 2; mt++)
        #pragma unroll
        for (int nt = 0; nt < 8; nt++)
            #pragma unroll
            for (int q = 0; q < 4; q++) acc[mt][nt][q] = 0.f;

    for (int kt = 0; kt < NKT; kt++) {
        CP_WAIT1();
        __syncthreads();
        const int nk = kt + STAGES - 1;
        if (nk < NKT) load_stage(nk % STAGES, nk);
        CP_COMMIT();

        const int st = kt % STAGES;
        const uint32_t aS = aU + st * A_STAGE_BYTES;
        const uint32_t bS = bU + st * B_STAGE_BYTES;

        #pragma unroll
        for (int s = 0; s < 2; s++) {       // two k16 steps inside BK=32
            uint32_t ar[2][4];
            #pragma unroll
            for (int mt = 0; mt < 2; mt++) {
                int row = wm * 32 + mt * 16 + (lane & 15);
                int cL = 2 * s + (lane >> 4);
                int ph = cL ^ ((row >> 1) & 3);
                ldm4(ar[mt], aS + row * 64 + ph * 16);
            }
            uint32_t br[4][4];
            #pragma unroll
            for (int np = 0; np < 4; np++) {
                int nrow = wn * 64 + np * 16 + (lane & 7) + ((lane >> 4) << 3);
                int cL = 2 * s + ((lane >> 3) & 1);
                int ph = cL ^ ((nrow >> 1) & 3);
                ldm4(br[np], bS + nrow * 64 + ph * 16);
            }
            #pragma unroll
            for (int mt = 0; mt < 2; mt++)
                #pragma unroll
                for (int np = 0; np < 4; np++) {
                    mma16816(acc[mt][np * 2 + 0], ar[mt], br[np][0], br[np][1]);
                    mma16816(acc[mt][np * 2 + 1], ar[mt], br[np][2], br[np][3]);
                }
        }
    }

    // epilogue: acc -> g_scores (fp32 row-major)
    #pragma unroll
    for (int mt = 0; mt < 2; mt++) {
        const int r0 = rowbase + wm * 32 + mt * 16 + (lane >> 2);
        #pragma unroll
        for (int nt = 0; nt < 8; nt++) {
            const int c0 = colbase + wn * 64 + nt * 8 + 2 * (lane & 3);
            float2* p0 = (float2*)(g_scores + (size_t)r0 * NP + c0);
            float2* p1 = (float2*)(g_scores + (size_t)(r0 + 8) * NP + c0);
            *p0 = make_float2(acc[mt][nt][0], acc[mt][nt][1]);
            *p1 = make_float2(acc[mt][nt][2], acc[mt][nt][3]);
        }
    }
}

// ---------------- kernel 4: coarse top-16 smallest per row ----------------
__device__ __forceinline__ void insert16(unsigned long long (&a)[16], unsigned long long key) {
    if (key < a[15]) {
        a[15] = key;
        #pragma unroll
        for (int q = 15; q > 0; q--)
            if (a[q] < a[q - 1]) { unsigned long long t = a[q]; a[q] = a[q - 1]; a[q - 1] = t; }
    }
}
__device__ __forceinline__ void merge16(unsigned long long (&a)[16], const unsigned long long (&b)[16]) {
    #pragma unroll
    for (int q = 0; q < 16; q++) { unsigned long long o = b[15 - q]; if (o < a[q]) a[q] = o; }
    #pragma unroll
    for (int kk = 8; kk >= 1; kk >>= 1) {
        #pragma unroll
        for (int i = 0; i < 16; i++) {
            if (!(i & kk)) {
                int j = i | kk;
                if (a[j] < a[i]) { unsigned long long t = a[i]; a[i] = a[j]; a[j] = t; }
            }
        }
    }
}
__global__ void topk16_kernel() {
    const int row = blockIdx.x;
    const float* s = g_scores + (size_t)row * NP;
    unsigned long long a[16];
    #pragma unroll
    for (int q = 0; q < 16; q++) a[q] = ~0ull;
    for (int i = threadIdx.x; i < NP; i += 128) {
        unsigned u = __float_as_uint(s[i]);
        u = (u & 0x80000000u) ? ~u : (u | 0x80000000u);
        insert16(a, ((unsigned long long)u << 32) | (unsigned)i);
    }
    #pragma unroll
    for (int off = 16; off; off >>= 1) {
        unsigned long long b[16];
        #pragma unroll
        for (int q = 0; q < 16; q++) b[q] = __shfl_xor_sync(0xffffffffu, a[q], off);
        merge16(a, b);
    }
    __shared__ unsigned long long sm[4][16];
    const int wid = threadIdx.x >> 5, lane = threadIdx.x & 31;
    if (lane == 0) {
        #pragma unroll
        for (int q = 0; q < 16; q++) sm[wid][q] = a[q];
    }
    __syncthreads();
    if (threadIdx.x == 0) {
        for (int w = 1; w < 4; w++) {
            unsigned long long b[16];
            #pragma unroll
            for (int q = 0; q < 16; q++) b[q] = sm[w][q];
            merge16(a, b);
        }
        #pragma unroll
        for (int q = 0; q < 16; q++) g_cand[row * CAND + q] = (int)(a[q] & 0xffffffffu);
    }
}

// ---------------- kernel 5: exact fp32 rescore of 16 candidates ----------------
__global__ void rescore_kernel(const float* __restrict__ x, const float* __restrict__ keys) {
    const int row = blockIdx.x;
    __shared__ float xs[KD];
    __shared__ unsigned long long ck[CAND];
    const int tid = threadIdx.x, wid = tid >> 5, lane = tid & 31;
    *(float4*)&xs[tid * 4] = *(const float4*)(x + (size_t)row * KD + tid * 4);
    __syncthreads();
    for (int c = wid; c < CAND; c += 4) {
        const int idx = g_cand[row * CAND + c];
        const float* kr = keys + (size_t)idx * KD;
        float sum = 0.f;
        #pragma unroll
        for (int j = 0; j < 16; j++) sum = fmaf(xs[lane + 32 * j], kr[lane + 32 * j], sum);
        #pragma unroll
        for (int o = 16; o; o >>= 1) sum += __shfl_xor_sync(0xffffffffu, sum, o);
        if (lane == 0) {
            float sc = sum * g_invk[idx];
            unsigned u = __float_as_uint(sc);
            u = (u & 0x80000000u) ? ~u : (u | 0x80000000u);
            ck[c] = ((unsigned long long)u << 32) | (unsigned)idx;
        }
    }
    __syncthreads();
    if (tid == 0) {
        #pragma unroll
        for (int q = 0; q < TOPK; q++) {
            unsigned long long best = ~0ull; int bi = 0;
            #pragma unroll
            for (int c = 0; c < CAND; c++) if (ck[c] < best) { best = ck[c]; bi = c; }
            ck[bi] = ~0ull;
            g_topidx[row * TOPK + q] = (int)(best & 0xffffffffu);
        }
    }
}

// ---------------- kernel 6: gather (streaming stores) ----------------
__global__ void gather_kernel(const float* __restrict__ pv, float* __restrict__ out) {
    const int b = blockIdx.x, j = blockIdx.y;
    const int idx = g_topidx[b * TOPK + j];
    const float4* src = (const float4*)(pv + (size_t)idx * ROW_ELEMS);
    float4* dst = (float4*)(out + (size_t)b * (TOPK * ROW_ELEMS) + (size_t)j * ROW_ELEMS);
    #pragma unroll 8
    for (int i = threadIdx.x; i < ROW_ELEMS / 4; i += 256)
        __stcs(dst + i, __ldg(src + i));
}

// ---------------- launcher ----------------
extern "C" void kernel_launch(void* const* d_in, const int* in_sizes, int n_in,
                              void* d_out, int out_size) {
    const float* x    = (const float*)d_in[0];   // (4096, 512)
    const float* keys = (const float*)d_in[1];   // (4096, 512)
    const float* pv   = (const float*)d_in[2];   // (4096, 16, 512)
    float* out = (float*)d_out;

    key_norm_kernel<<<NP / 8, dim3(32, 8)>>>(keys);
    convert_kernel<<<(NB * KD / 8) / 256, 256>>>(x, 0);
    convert_kernel<<<(NP * KD / 8) / 256, 256>>>(keys, 1);
    coarse_gemm<<<dim3(NP / BN, NB / BM), 256>>>();
    topk16_kernel<<<NB, 128>>>();
    rescore_kernel<<<NB, 128>>>(x, keys);
    gather_kernel<<<dim3(NB, TOPK), 256>>>(pv, out);
}

// round 5
// speedup vs baseline: 1.5708x; 1.0322x over previous
#include <cuda_runtime.h>
#include <cuda_bf16.h>
#include <stdint.h>
#include <math.h>

// ---------------- problem constants ----------------
#define KD    512
#define TOPK  4
#define ROW_ELEMS 8192
#define NB 4096
#define NP 4096
#define CAND 16
#define NTILE (NP/128)       // 32 column tiles

// ---------------- GEMM tiling ----------------
#define BM 128
#define BN 128
#define BK 32
#define STAGES 3
#define NKT (KD/BK)          // 16 k-steps
#define A_STAGE_BYTES (BM*BK*2)   // 8192
#define B_STAGE_BYTES (BN*BK*2)   // 8192

// ---------------- device scratch ----------------
__device__ float g_invk[NP];
__device__ unsigned long long g_tilecand[(size_t)NB * NTILE * 8];  // 8 MB
__device__ int   g_cand[NB * CAND];
__device__ int   g_topidx[NB * TOPK];
__device__ __nv_bfloat16 g_Xb[(size_t)NB * KD];      // 4 MB
__device__ __nv_bfloat16 g_Kb[(size_t)NP * KD];      // 4 MB (pre-scaled by invk)

// ---------------- helpers ----------------
__device__ __forceinline__ uint32_t smem_to_u32(const void* p) {
    uint32_t a;
    asm("{ .reg .u64 t; cvta.to.shared.u64 t, %1; cvt.u32.u64 %0, t; }" : "=r"(a) : "l"(p));
    return a;
}
__device__ __forceinline__ void cp16(uint32_t dst, const void* src) {
    asm volatile("cp.async.cg.shared.global [%0], [%1], 16;" :: "r"(dst), "l"(src) : "memory");
}
#define CP_COMMIT() asm volatile("cp.async.commit_group;" ::: "memory")
#define CP_WAIT1()  asm volatile("cp.async.wait_group 1;" ::: "memory")
#define CP_WAIT0()  asm volatile("cp.async.wait_group 0;" ::: "memory")

__device__ __forceinline__ void ldm4(uint32_t* r, uint32_t a) {
    asm volatile("ldmatrix.sync.aligned.m8n8.x4.shared.b16 {%0,%1,%2,%3}, [%4];"
                 : "=r"(r[0]), "=r"(r[1]), "=r"(r[2]), "=r"(r[3]) : "r"(a));
}
__device__ __forceinline__ void mma16816(float* c, const uint32_t* a, uint32_t b0, uint32_t b1) {
    asm volatile("mma.sync.aligned.m16n8k16.row.col.f32.bf16.bf16.f32 "
                 "{%0,%1,%2,%3}, {%4,%5,%6,%7}, {%8,%9}, {%0,%1,%2,%3};"
                 : "+f"(c[0]), "+f"(c[1]), "+f"(c[2]), "+f"(c[3])
                 : "r"(a[0]), "r"(a[1]), "r"(a[2]), "r"(a[3]), "r"(b0), "r"(b1));
}

// sortable-ascending float map (smallest cos first)
__device__ __forceinline__ unsigned fmap(float v) {
    unsigned u = __float_as_uint(v);
    return (u & 0x80000000u) ? ~u : (u | 0x80000000u);
}

// ---- sorted small-list primitives (ascending, keep smallest) ----
__device__ __forceinline__ void insert8(unsigned long long (&a)[8], unsigned long long key) {
    if (key < a[7]) {
        a[7] = key;
        #pragma unroll
        for (int q = 7; q > 0; q--)
            if (a[q] < a[q - 1]) { unsigned long long t = a[q]; a[q] = a[q - 1]; a[q - 1] = t; }
    }
}
__device__ __forceinline__ void merge8(unsigned long long (&a)[8], const unsigned long long (&b)[8]) {
    #pragma unroll
    for (int q = 0; q < 8; q++) { unsigned long long o = b[7 - q]; if (o < a[q]) a[q] = o; }
    #pragma unroll
    for (int kk = 4; kk >= 1; kk >>= 1)
        #pragma unroll
        for (int i = 0; i < 8; i++)
            if (!(i & kk)) { int j = i | kk; if (a[j] < a[i]) { unsigned long long t = a[i]; a[i] = a[j]; a[j] = t; } }
}
__device__ __forceinline__ void insert16(unsigned long long (&a)[16], unsigned long long key) {
    if (key < a[15]) {
        a[15] = key;
        #pragma unroll
        for (int q = 15; q > 0; q--)
            if (a[q] < a[q - 1]) { unsigned long long t = a[q]; a[q] = a[q - 1]; a[q - 1] = t; }
    }
}
__device__ __forceinline__ void merge16(unsigned long long (&a)[16], const unsigned long long (&b)[16]) {
    #pragma unroll
    for (int q = 0; q < 16; q++) { unsigned long long o = b[15 - q]; if (o < a[q]) a[q] = o; }
    #pragma unroll
    for (int kk = 8; kk >= 1; kk >>= 1)
        #pragma unroll
        for (int i = 0; i < 16; i++)
            if (!(i & kk)) { int j = i | kk; if (a[j] < a[i]) { unsigned long long t = a[i]; a[i] = a[j]; a[j] = t; } }
}

// ---------------- kernel 1: per-key inverse L2 norm ----------------
__global__ void key_norm_kernel(const float* __restrict__ keys) {
    int row = blockIdx.x * blockDim.y + threadIdx.y;
    const float* kr = keys + (size_t)row * KD;
    float s = 0.f;
    for (int i = threadIdx.x; i < KD; i += 32) { float v = kr[i]; s = fmaf(v, v, s); }
    #pragma unroll
    for (int o = 16; o; o >>= 1) s += __shfl_xor_sync(0xffffffffu, s, o);
    if (threadIdx.x == 0) {
        double d = (double)fmaxf(s, 1e-12f);
        g_invk[row] = (float)(1.0 / sqrt(d));
    }
}

// ---------------- kernel 2: fp32 -> bf16 convert (row-major) ----------------
__device__ __forceinline__ unsigned pack_bf16(float a, float b) {
    __nv_bfloat16 ha = __float2bfloat16_rn(a);
    __nv_bfloat16 hb = __float2bfloat16_rn(b);
    unsigned short ua = *(unsigned short*)&ha;
    unsigned short ub = *(unsigned short*)&hb;
    return (unsigned)ua | ((unsigned)ub << 16);
}
__global__ void convert_kernel(const float* __restrict__ src, int which) {
    int i = blockIdx.x * blockDim.x + threadIdx.x;   // one 8-elem chunk each
    const float* s = src + (size_t)i * 8;
    float4 f0 = *(const float4*)s;
    float4 f1 = *(const float4*)(s + 4);
    if (which) {
        float iv = g_invk[i >> 6];
        f0.x *= iv; f0.y *= iv; f0.z *= iv; f0.w *= iv;
        f1.x *= iv; f1.y *= iv; f1.z *= iv; f1.w *= iv;
    }
    uint4 o;
    o.x = pack_bf16(f0.x, f0.y); o.y = pack_bf16(f0.z, f0.w);
    o.z = pack_bf16(f1.x, f1.y); o.w = pack_bf16(f1.z, f1.w);
    uint4* dst = which ? (uint4*)g_Kb : (uint4*)g_Xb;
    dst[i] = o;
}

// ---------------- kernel 3: coarse bf16 HMMA GEMM + fused per-tile top-8 ----
__global__ void __launch_bounds__(256, 2) coarse_gemm() {
    __shared__ __align__(1024) char sA[STAGES][A_STAGE_BYTES];
    __shared__ __align__(1024) char sB[STAGES][B_STAGE_BYTES];
    const uint32_t aU = smem_to_u32(sA);
    const uint32_t bU = smem_to_u32(sB);
    const int t = threadIdx.x;
    const int rowbase = blockIdx.y * BM;
    const int colbase = blockIdx.x * BN;
    const __nv_bfloat16* Xb = g_Xb;
    const __nv_bfloat16* Kb = g_Kb;

    auto load_stage = [&](int st, int kt) {
        const int k0 = kt * BK;
        #pragma unroll
        for (int i = 0; i < 2; i++) {
            int ch = t + i * 256;
            int row = ch >> 2, c = ch & 3;
            int ph = c ^ ((row >> 1) & 3);
            cp16(aU + st * A_STAGE_BYTES + row * 64 + ph * 16,
                 Xb + (size_t)(rowbase + row) * KD + k0 + c * 8);
        }
        #pragma unroll
        for (int i = 0; i < 2; i++) {
            int ch = t + i * 256;
            int row = ch >> 2, c = ch & 3;
            int ph = c ^ ((row >> 1) & 3);
            cp16(bU + st * B_STAGE_BYTES + row * 64 + ph * 16,
                 Kb + (size_t)(colbase + row) * KD + k0 + c * 8);
        }
    };

    load_stage(0, 0); CP_COMMIT();
    load_stage(1, 1); CP_COMMIT();

    const int wid = t >> 5, lane = t & 31;
    const int wm = wid & 3, wn = wid >> 2;   // 4x2 warp grid: 32-row x 64-col tiles

    float acc[2][8][4];
    #pragma unroll
    for (int mt = 0; mt < 2; mt++)
        #pragma unroll
        for (int nt = 0; nt < 8; nt++)
            #pragma unroll
            for (int q = 0; q < 4; q++) acc[mt][nt][q] = 0.f;

    for (int kt = 0; kt < NKT; kt++) {
        CP_WAIT1();
        __syncthreads();
        const int nk = kt + STAGES - 1;
        if (nk < NKT) load_stage(nk % STAGES, nk);
        CP_COMMIT();

        const int st = kt % STAGES;
        const uint32_t aS = aU + st * A_STAGE_BYTES;
        const uint32_t bS = bU + st * B_STAGE_BYTES;

        #pragma unroll
        for (int s = 0; s < 2; s++) {
            uint32_t ar[2][4];
            #pragma unroll
            for (int mt = 0; mt < 2; mt++) {
                int row = wm * 32 + mt * 16 + (lane & 15);
                int cL = 2 * s + (lane >> 4);
                int ph = cL ^ ((row >> 1) & 3);
                ldm4(ar[mt], aS + row * 64 + ph * 16);
            }
            uint32_t br[4][4];
            #pragma unroll
            for (int np = 0; np < 4; np++) {
                int nrow = wn * 64 + np * 16 + (lane & 7) + ((lane >> 4) << 3);
                int cL = 2 * s + ((lane >> 3) & 1);
                int ph = cL ^ ((nrow >> 1) & 3);
                ldm4(br[np], bS + nrow * 64 + ph * 16);
            }
            #pragma unroll
            for (int mt = 0; mt < 2; mt++)
                #pragma unroll
                for (int np = 0; np < 4; np++) {
                    mma16816(acc[mt][np * 2 + 0], ar[mt], br[np][0], br[np][1]);
                    mma16816(acc[mt][np * 2 + 1], ar[mt], br[np][2], br[np][3]);
                }
        }
    }

    // ---- fused epilogue: per-row top-8 of this 128x128 tile ----
    CP_WAIT0();
    __syncthreads();
    // reuse sA as candidate buffer [2 warp-cols][128 rows][8] u64 = 16 KB (<24 KB)
    unsigned long long* cbuf = (unsigned long long*)sA;

    const int g = lane >> 2;      // row within 8-group
    const int sub = lane & 3;     // column sub-slot

    #pragma unroll
    for (int mt = 0; mt < 2; mt++) {
        #pragma unroll
        for (int h = 0; h < 2; h++) {
            unsigned long long a8[8];
            #pragma unroll
            for (int q = 0; q < 8; q++) a8[q] = ~0ull;
            #pragma unroll
            for (int nt = 0; nt < 8; nt++) {
                #pragma unroll
                for (int j = 0; j < 2; j++) {
                    float v = acc[mt][nt][2 * h + j];
                    unsigned col = (unsigned)(colbase + wn * 64 + nt * 8 + 2 * sub + j);
                    insert8(a8, ((unsigned long long)fmap(v) << 32) | col);
                }
            }
            // merge across the 4 lanes holding the same row
            #pragma unroll
            for (int off = 1; off <= 2; off <<= 1) {
                unsigned long long b8[8];
                #pragma unroll
                for (int q = 0; q < 8; q++) b8[q] = __shfl_xor_sync(0xffffffffu, a8[q], off);
                merge8(a8, b8);
            }
            const int rloc = wm * 32 + mt * 16 + h * 8 + g;   // 0..127
            if (sub == 0) {
                #pragma unroll
                for (int q = 0; q < 8; q++) cbuf[((size_t)wn * 128 + rloc) * 8 + q] = a8[q];
            }
        }
    }
    __syncthreads();

    // threads 0..127: merge the two warp-column halves, write 8 u64 per row
    if (t < 128) {
        unsigned long long a8[8], b8[8];
        #pragma unroll
        for (int q = 0; q < 8; q++) { a8[q] = cbuf[(size_t)t * 8 + q]; b8[q] = cbuf[(size_t)(128 + t) * 8 + q]; }
        merge8(a8, b8);
        unsigned long long* dst = g_tilecand + ((size_t)(rowbase + t) * NTILE + blockIdx.x) * 8;
        #pragma unroll
        for (int q = 0; q < 8; q++) dst[q] = a8[q];
    }
}

// ---------------- kernel 4: merge per-tile top-8 -> coarse top-16 ----------
__global__ void cand_merge_kernel() {
    const int row = blockIdx.x * 4 + (threadIdx.x >> 5);
    const int lane = threadIdx.x & 31;
    const unsigned long long* src = g_tilecand + (size_t)row * (NTILE * 8);
    unsigned long long a[16];
    #pragma unroll
    for (int q = 0; q < 16; q++) a[q] = ~0ull;
    // lane <-> tile (NTILE == 32)
    #pragma unroll
    for (int q = 0; q < 8; q++) insert16(a, src[lane * 8 + q]);
    #pragma unroll
    for (int off = 16; off; off >>= 1) {
        unsigned long long b[16];
        #pragma unroll
        for (int q = 0; q < 16; q++) b[q] = __shfl_xor_sync(0xffffffffu, a[q], off);
        merge16(a, b);
    }
    if (lane < 16) g_cand[row * CAND + lane] = (int)(a[lane] & 0xffffffffu);
}

// ---------------- kernel 5: exact fp32 rescore of 16 candidates ----------------
__global__ void rescore_kernel(const float* __restrict__ x, const float* __restrict__ keys) {
    const int row = blockIdx.x;
    __shared__ float xs[KD];
    __shared__ unsigned long long ck[CAND];
    const int tid = threadIdx.x, wid = tid >> 5, lane = tid & 31;
    *(float4*)&xs[tid * 4] = *(const float4*)(x + (size_t)row * KD + tid * 4);
    __syncthreads();
    for (int c = wid; c < CAND; c += 4) {
        const int idx = g_cand[row * CAND + c];
        const float* kr = keys + (size_t)idx * KD;
        float sum = 0.f;
        #pragma unroll
        for (int j = 0; j < 16; j++) sum = fmaf(xs[lane + 32 * j], kr[lane + 32 * j], sum);
        #pragma unroll
        for (int o = 16; o; o >>= 1) sum += __shfl_xor_sync(0xffffffffu, sum, o);
        if (lane == 0) {
            float sc = sum * g_invk[idx];
            ck[c] = ((unsigned long long)fmap(sc) << 32) | (unsigned)idx;
        }
    }
    __syncthreads();
    if (tid == 0) {
        #pragma unroll
        for (int q = 0; q < TOPK; q++) {
            unsigned long long best = ~0ull; int bi = 0;
            #pragma unroll
            for (int c = 0; c < CAND; c++) if (ck[c] < best) { best = ck[c]; bi = c; }
            ck[bi] = ~0ull;
            g_topidx[row * TOPK + q] = (int)(best & 0xffffffffu);
        }
    }
}

// ---------------- kernel 6: gather (streaming stores) ----------------
__global__ void gather_kernel(const float* __restrict__ pv, float* __restrict__ out) {
    const int b = blockIdx.x, j = blockIdx.y;
    const int idx = g_topidx[b * TOPK + j];
    const float4* src = (const float4*)(pv + (size_t)idx * ROW_ELEMS);
    float4* dst = (float4*)(out + (size_t)b * (TOPK * ROW_ELEMS) + (size_t)j * ROW_ELEMS);
    #pragma unroll 8
    for (int i = threadIdx.x; i < ROW_ELEMS / 4; i += 256)
        __stcs(dst + i, __ldg(src + i));
}

// ---------------- launcher ----------------
extern "C" void kernel_launch(void* const* d_in, const int* in_sizes, int n_in,
                              void* d_out, int out_size) {
    const float* x    = (const float*)d_in[0];   // (4096, 512)
    const float* keys = (const float*)d_in[1];   // (4096, 512)
    const float* pv   = (const float*)d_in[2];   // (4096, 16, 512)
    float* out = (float*)d_out;

    key_norm_kernel<<<NP / 8, dim3(32, 8)>>>(keys);
    convert_kernel<<<(NB * KD / 8) / 256, 256>>>(x, 0);
    convert_kernel<<<(NP * KD / 8) / 256, 256>>>(keys, 1);
    coarse_gemm<<<dim3(NP / BN, NB / BM), 256>>>();
    cand_merge_kernel<<<NB / 4, 128>>>();
    rescore_kernel<<<NB, 128>>>(x, keys);
    gather_kernel<<<dim3(NB, TOPK), 256>>>(pv, out);
}

// round 6
// speedup vs baseline: 2.4494x; 1.5594x over previous
#include <cuda_runtime.h>
#include <cuda_bf16.h>
#include <stdint.h>
#include <math.h>

// ---------------- problem constants ----------------
#define KD    512
#define TOPK  4
#define ROW_ELEMS 8192
#define NB 4096
#define NP 4096
#define CAND 16
#define NTILE (NP/128)       // 32 column tiles

// ---------------- GEMM tiling ----------------
#define BM 128
#define BN 128
#define BK 32
#define STAGES 3
#define NKT (KD/BK)          // 16 k-steps
#define A_STAGE_BYTES (BM*BK*2)   // 8192
#define B_STAGE_BYTES (BN*BK*2)   // 8192

// ---------------- device scratch ----------------
__device__ float g_invk[NP];
__device__ unsigned g_tilecand[(size_t)NB * NTILE * 8];  // 4 MB, u32 keys
__device__ int   g_cand[NB * CAND];
__device__ int   g_topidx[NB * TOPK];
__device__ __nv_bfloat16 g_Xb[(size_t)NB * KD];      // 4 MB
__device__ __nv_bfloat16 g_Kb[(size_t)NP * KD];      // 4 MB (pre-scaled by invk)

// ---------------- helpers ----------------
__device__ __forceinline__ uint32_t smem_to_u32(const void* p) {
    uint32_t a;
    asm("{ .reg .u64 t; cvta.to.shared.u64 t, %1; cvt.u32.u64 %0, t; }" : "=r"(a) : "l"(p));
    return a;
}
__device__ __forceinline__ void cp16(uint32_t dst, const void* src) {
    asm volatile("cp.async.cg.shared.global [%0], [%1], 16;" :: "r"(dst), "l"(src) : "memory");
}
#define CP_COMMIT() asm volatile("cp.async.commit_group;" ::: "memory")
#define CP_WAIT1()  asm volatile("cp.async.wait_group 1;" ::: "memory")
#define CP_WAIT0()  asm volatile("cp.async.wait_group 0;" ::: "memory")

__device__ __forceinline__ void ldm4(uint32_t* r, uint32_t a) {
    asm volatile("ldmatrix.sync.aligned.m8n8.x4.shared.b16 {%0,%1,%2,%3}, [%4];"
                 : "=r"(r[0]), "=r"(r[1]), "=r"(r[2]), "=r"(r[3]) : "r"(a));
}
__device__ __forceinline__ void mma16816(float* c, const uint32_t* a, uint32_t b0, uint32_t b1) {
    asm volatile("mma.sync.aligned.m16n8k16.row.col.f32.bf16.bf16.f32 "
                 "{%0,%1,%2,%3}, {%4,%5,%6,%7}, {%8,%9}, {%0,%1,%2,%3};"
                 : "+f"(c[0]), "+f"(c[1]), "+f"(c[2]), "+f"(c[3])
                 : "r"(a[0]), "r"(a[1]), "r"(a[2]), "r"(a[3]), "r"(b0), "r"(b1));
}

// sortable-ascending float map (smallest cos first)
__device__ __forceinline__ unsigned fmap(float v) {
    unsigned u = __float_as_uint(v);
    return (u & 0x80000000u) ? ~u : (u | 0x80000000u);
}

// ---- u32 sorted small-list primitives (ascending, keep smallest) ----
__device__ __forceinline__ void insert8(unsigned (&a)[8], unsigned key) {
    if (key < a[7]) {
        a[7] = key;
        #pragma unroll
        for (int q = 7; q > 0; q--)
            if (a[q] < a[q - 1]) { unsigned t = a[q]; a[q] = a[q - 1]; a[q - 1] = t; }
    }
}
__device__ __forceinline__ void merge8(unsigned (&a)[8], const unsigned (&b)[8]) {
    #pragma unroll
    for (int q = 0; q < 8; q++) { unsigned o = b[7 - q]; if (o < a[q]) a[q] = o; }
    #pragma unroll
    for (int kk = 4; kk >= 1; kk >>= 1)
        #pragma unroll
        for (int i = 0; i < 8; i++)
            if (!(i & kk)) { int j = i | kk; if (a[j] < a[i]) { unsigned t = a[i]; a[i] = a[j]; a[j] = t; } }
}
__device__ __forceinline__ void insert16(unsigned (&a)[16], unsigned key) {
    if (key < a[15]) {
        a[15] = key;
        #pragma unroll
        for (int q = 15; q > 0; q--)
            if (a[q] < a[q - 1]) { unsigned t = a[q]; a[q] = a[q - 1]; a[q - 1] = t; }
    }
}
__device__ __forceinline__ void merge16(unsigned (&a)[16], const unsigned (&b)[16]) {
    #pragma unroll
    for (int q = 0; q < 16; q++) { unsigned o = b[15 - q]; if (o < a[q]) a[q] = o; }
    #pragma unroll
    for (int kk = 8; kk >= 1; kk >>= 1)
        #pragma unroll
        for (int i = 0; i < 16; i++)
            if (!(i & kk)) { int j = i | kk; if (a[j] < a[i]) { unsigned t = a[i]; a[i] = a[j]; a[j] = t; } }
}

// ---------------- kernel 1: per-key inverse L2 norm ----------------
__global__ void key_norm_kernel(const float* __restrict__ keys) {
    int row = blockIdx.x * blockDim.y + threadIdx.y;
    const float* kr = keys + (size_t)row * KD;
    float s = 0.f;
    for (int i = threadIdx.x; i < KD; i += 32) { float v = kr[i]; s = fmaf(v, v, s); }
    #pragma unroll
    for (int o = 16; o; o >>= 1) s += __shfl_xor_sync(0xffffffffu, s, o);
    if (threadIdx.x == 0) {
        double d = (double)fmaxf(s, 1e-12f);
        g_invk[row] = (float)(1.0 / sqrt(d));
    }
}

// ---------------- kernel 2: fp32 -> bf16 convert (row-major) ----------------
__device__ __forceinline__ unsigned pack_bf16(float a, float b) {
    __nv_bfloat16 ha = __float2bfloat16_rn(a);
    __nv_bfloat16 hb = __float2bfloat16_rn(b);
    unsigned short ua = *(unsigned short*)&ha;
    unsigned short ub = *(unsigned short*)&hb;
    return (unsigned)ua | ((unsigned)ub << 16);
}
__global__ void convert_kernel(const float* __restrict__ src, int which) {
    int i = blockIdx.x * blockDim.x + threadIdx.x;
    const float* s = src + (size_t)i * 8;
    float4 f0 = *(const float4*)s;
    float4 f1 = *(const float4*)(s + 4);
    if (which) {
        float iv = g_invk[i >> 6];
        f0.x *= iv; f0.y *= iv; f0.z *= iv; f0.w *= iv;
        f1.x *= iv; f1.y *= iv; f1.z *= iv; f1.w *= iv;
    }
    uint4 o;
    o.x = pack_bf16(f0.x, f0.y); o.y = pack_bf16(f0.z, f0.w);
    o.z = pack_bf16(f1.x, f1.y); o.w = pack_bf16(f1.z, f1.w);
    uint4* dst = which ? (uint4*)g_Kb : (uint4*)g_Xb;
    dst[i] = o;
}

// ---------------- kernel 3: coarse bf16 HMMA GEMM + fused per-tile top-8 ----
__global__ void __launch_bounds__(256) coarse_gemm() {
    __shared__ __align__(1024) char sA[STAGES][A_STAGE_BYTES];
    __shared__ __align__(1024) char sB[STAGES][B_STAGE_BYTES];
    const uint32_t aU = smem_to_u32(sA);
    const uint32_t bU = smem_to_u32(sB);
    const int t = threadIdx.x;
    const int rowbase = blockIdx.y * BM;
    const int colbase = blockIdx.x * BN;
    const __nv_bfloat16* Xb = g_Xb;
    const __nv_bfloat16* Kb = g_Kb;

    auto load_stage = [&](int st, int kt) {
        const int k0 = kt * BK;
        #pragma unroll
        for (int i = 0; i < 2; i++) {
            int ch = t + i * 256;
            int row = ch >> 2, c = ch & 3;
            int ph = c ^ ((row >> 1) & 3);
            cp16(aU + st * A_STAGE_BYTES + row * 64 + ph * 16,
                 Xb + (size_t)(rowbase + row) * KD + k0 + c * 8);
        }
        #pragma unroll
        for (int i = 0; i < 2; i++) {
            int ch = t + i * 256;
            int row = ch >> 2, c = ch & 3;
            int ph = c ^ ((row >> 1) & 3);
            cp16(bU + st * B_STAGE_BYTES + row * 64 + ph * 16,
                 Kb + (size_t)(colbase + row) * KD + k0 + c * 8);
        }
    };

    load_stage(0, 0); CP_COMMIT();
    load_stage(1, 1); CP_COMMIT();

    const int wid = t >> 5, lane = t & 31;
    const int wm = wid & 3, wn = wid >> 2;   // 4x2 warp grid: 32-row x 64-col tiles

    float acc[2][8][4];
    #pragma unroll
    for (int mt = 0; mt < 2; mt++)
        #pragma unroll
        for (int nt = 0; nt < 8; nt++)
            #pragma unroll
            for (int q = 0; q < 4; q++) acc[mt][nt][q] = 0.f;

    for (int kt = 0; kt < NKT; kt++) {
        CP_WAIT1();
        __syncthreads();
        const int nk = kt + STAGES - 1;
        if (nk < NKT) load_stage(nk % STAGES, nk);
        CP_COMMIT();

        const int st = kt % STAGES;
        const uint32_t aS = aU + st * A_STAGE_BYTES;
        const uint32_t bS = bU + st * B_STAGE_BYTES;

        #pragma unroll
        for (int s = 0; s < 2; s++) {
            uint32_t ar[2][4];
            #pragma unroll
            for (int mt = 0; mt < 2; mt++) {
                int row = wm * 32 + mt * 16 + (lane & 15);
                int cL = 2 * s + (lane >> 4);
                int ph = cL ^ ((row >> 1) & 3);
                ldm4(ar[mt], aS + row * 64 + ph * 16);
            }
            uint32_t br[4][4];
            #pragma unroll
            for (int np = 0; np < 4; np++) {
                int nrow = wn * 64 + np * 16 + (lane & 7) + ((lane >> 4) << 3);
                int cL = 2 * s + ((lane >> 3) & 1);
                int ph = cL ^ ((nrow >> 1) & 3);
                ldm4(br[np], bS + nrow * 64 + ph * 16);
            }
            #pragma unroll
            for (int mt = 0; mt < 2; mt++)
                #pragma unroll
                for (int np = 0; np < 4; np++) {
                    mma16816(acc[mt][np * 2 + 0], ar[mt], br[np][0], br[np][1]);
                    mma16816(acc[mt][np * 2 + 1], ar[mt], br[np][2], br[np][3]);
                }
        }
    }

    // ---- fused epilogue: per-row top-8 of this 128x128 tile (u32 keys) ----
    // key = (fmap(score) & ~0xFFF) | global_col  (20 score bits + 12 col bits)
    CP_WAIT0();
    __syncthreads();
    unsigned* cbuf = (unsigned*)sA;   // [2 warp-cols][128 rows][8] u32 = 8 KB

    const int g = lane >> 2;      // row within 8-group
    const int sub = lane & 3;     // column sub-slot

    #pragma unroll
    for (int mt = 0; mt < 2; mt++) {
        #pragma unroll
        for (int h = 0; h < 2; h++) {
            unsigned a8[8];
            #pragma unroll
            for (int q = 0; q < 8; q++) a8[q] = 0xFFFFFFFFu;
            #pragma unroll
            for (int nt = 0; nt < 8; nt++) {
                #pragma unroll
                for (int j = 0; j < 2; j++) {
                    float v = acc[mt][nt][2 * h + j];
                    unsigned col = (unsigned)(colbase + wn * 64 + nt * 8 + 2 * sub + j);
                    insert8(a8, (fmap(v) & 0xFFFFF000u) | col);
                }
            }
            #pragma unroll
            for (int off = 1; off <= 2; off <<= 1) {
                unsigned b8[8];
                #pragma unroll
                for (int q = 0; q < 8; q++) b8[q] = __shfl_xor_sync(0xffffffffu, a8[q], off);
                merge8(a8, b8);
            }
            const int rloc = wm * 32 + mt * 16 + h * 8 + g;   // 0..127
            if (sub == 0) {
                #pragma unroll
                for (int q = 0; q < 8; q++) cbuf[(wn * 128 + rloc) * 8 + q] = a8[q];
            }
        }
    }
    __syncthreads();

    if (t < 128) {
        unsigned a8[8], b8[8];
        #pragma unroll
        for (int q = 0; q < 8; q++) { a8[q] = cbuf[t * 8 + q]; b8[q] = cbuf[(128 + t) * 8 + q]; }
        merge8(a8, b8);
        unsigned* dst = g_tilecand + ((size_t)(rowbase + t) * NTILE + blockIdx.x) * 8;
        #pragma unroll
        for (int q = 0; q < 8; q++) dst[q] = a8[q];
    }
}

// ---------------- kernel 4: merge per-tile top-8 -> coarse top-16 ----------
__global__ void cand_merge_kernel() {
    const int row = blockIdx.x * 4 + (threadIdx.x >> 5);
    const int lane = threadIdx.x & 31;
    const unsigned* src = g_tilecand + (size_t)row * (NTILE * 8);
    unsigned a[16];
    #pragma unroll
    for (int q = 0; q < 16; q++) a[q] = 0xFFFFFFFFu;
    #pragma unroll
    for (int q = 0; q < 8; q++) insert16(a, src[lane * 8 + q]);   // lane <-> tile
    #pragma unroll
    for (int off = 16; off; off >>= 1) {
        unsigned b[16];
        #pragma unroll
        for (int q = 0; q < 16; q++) b[q] = __shfl_xor_sync(0xffffffffu, a[q], off);
        merge16(a, b);
    }
    if (lane < 16) g_cand[row * CAND + lane] = (int)(a[lane] & 0xFFFu);
}

// ---------------- kernel 5: exact fp32 rescore of 16 candidates ----------------
__global__ void rescore_kernel(const float* __restrict__ x, const float* __restrict__ keys) {
    const int row = blockIdx.x;
    __shared__ float xs[KD];
    __shared__ unsigned long long ck[CAND];
    const int tid = threadIdx.x, wid = tid >> 5, lane = tid & 31;
    *(float4*)&xs[tid * 4] = *(const float4*)(x + (size_t)row * KD + tid * 4);
    __syncthreads();
    for (int c = wid; c < CAND; c += 4) {
        const int idx = g_cand[row * CAND + c];
        const float* kr = keys + (size_t)idx * KD;
        float sum = 0.f;
        #pragma unroll
        for (int j = 0; j < 16; j++) sum = fmaf(xs[lane + 32 * j], kr[lane + 32 * j], sum);
        #pragma unroll
        for (int o = 16; o; o >>= 1) sum += __shfl_xor_sync(0xffffffffu, sum, o);
        if (lane == 0) {
            float sc = sum * g_invk[idx];
            ck[c] = ((unsigned long long)fmap(sc) << 32) | (unsigned)idx;
        }
    }
    __syncthreads();
    if (tid == 0) {
        #pragma unroll
        for (int q = 0; q < TOPK; q++) {
            unsigned long long best = ~0ull; int bi = 0;
            #pragma unroll
            for (int c = 0; c < CAND; c++) if (ck[c] < best) { best = ck[c]; bi = c; }
            ck[bi] = ~0ull;
            g_topidx[row * TOPK + q] = (int)(best & 0xffffffffu);
        }
    }
}

// ---------------- kernel 6: gather (streaming stores) ----------------
__global__ void gather_kernel(const float* __restrict__ pv, float* __restrict__ out) {
    const int b = blockIdx.x, j = blockIdx.y;
    const int idx = g_topidx[b * TOPK + j];
    const float4* src = (const float4*)(pv + (size_t)idx * ROW_ELEMS);
    float4* dst = (float4*)(out + (size_t)b * (TOPK * ROW_ELEMS) + (size_t)j * ROW_ELEMS);
    #pragma unroll 8
    for (int i = threadIdx.x; i < ROW_ELEMS / 4; i += 256)
        __stcs(dst + i, __ldg(src + i));
}

// ---------------- launcher ----------------
extern "C" void kernel_launch(void* const* d_in, const int* in_sizes, int n_in,
                              void* d_out, int out_size) {
    const float* x    = (const float*)d_in[0];   // (4096, 512)
    const float* keys = (const float*)d_in[1];   // (4096, 512)
    const float* pv   = (const float*)d_in[2];   // (4096, 16, 512)
    float* out = (float*)d_out;

    key_norm_kernel<<<NP / 8, dim3(32, 8)>>>(keys);
    convert_kernel<<<(NB * KD / 8) / 256, 256>>>(x, 0);
    convert_kernel<<<(NP * KD / 8) / 256, 256>>>(keys, 1);
    coarse_gemm<<<dim3(NP / BN, NB / BM), 256>>>();
    cand_merge_kernel<<<NB / 4, 128>>>();
    rescore_kernel<<<NB, 128>>>(x, keys);
    gather_kernel<<<dim3(NB, TOPK), 256>>>(pv, out);
}

// round 7
// speedup vs baseline: 2.5173x; 1.0277x over previous
#include <cuda_runtime.h>
#include <cuda_bf16.h>
#include <stdint.h>
#include <math.h>

// ---------------- problem constants ----------------
#define KD    512
#define TOPK  4
#define ROW_ELEMS 8192
#define NB 4096
#define NP 4096
#define CAND 16
#define NTILE (NP/128)       // 32 column tiles

// ---------------- GEMM tiling ----------------
#define BM 128
#define BN 128
#define BK 32
#define STAGES 3
#define NKT (KD/BK)          // 16 k-steps
#define A_STAGE_BYTES (BM*BK*2)   // 8192
#define B_STAGE_BYTES (BN*BK*2)   // 8192

// ---------------- device scratch ----------------
__device__ float g_invk[NP];
__device__ unsigned g_tilecand[(size_t)NB * NTILE * 4];  // 2 MB, u32 keys
__device__ int   g_cand[NB * CAND];
__device__ int   g_topidx[NB * TOPK];
__device__ __nv_bfloat16 g_Xb[(size_t)NB * KD];      // 4 MB
__device__ __nv_bfloat16 g_Kb[(size_t)NP * KD];      // 4 MB (pre-scaled by invk)

// ---------------- helpers ----------------
__device__ __forceinline__ uint32_t smem_to_u32(const void* p) {
    uint32_t a;
    asm("{ .reg .u64 t; cvta.to.shared.u64 t, %1; cvt.u32.u64 %0, t; }" : "=r"(a) : "l"(p));
    return a;
}
__device__ __forceinline__ void cp16(uint32_t dst, const void* src) {
    asm volatile("cp.async.cg.shared.global [%0], [%1], 16;" :: "r"(dst), "l"(src) : "memory");
}
#define CP_COMMIT() asm volatile("cp.async.commit_group;" ::: "memory")
#define CP_WAIT1()  asm volatile("cp.async.wait_group 1;" ::: "memory")
#define CP_WAIT0()  asm volatile("cp.async.wait_group 0;" ::: "memory")

__device__ __forceinline__ void ldm4(uint32_t* r, uint32_t a) {
    asm volatile("ldmatrix.sync.aligned.m8n8.x4.shared.b16 {%0,%1,%2,%3}, [%4];"
                 : "=r"(r[0]), "=r"(r[1]), "=r"(r[2]), "=r"(r[3]) : "r"(a));
}
__device__ __forceinline__ void mma16816(float* c, const uint32_t* a, uint32_t b0, uint32_t b1) {
    asm volatile("mma.sync.aligned.m16n8k16.row.col.f32.bf16.bf16.f32 "
                 "{%0,%1,%2,%3}, {%4,%5,%6,%7}, {%8,%9}, {%0,%1,%2,%3};"
                 : "+f"(c[0]), "+f"(c[1]), "+f"(c[2]), "+f"(c[3])
                 : "r"(a[0]), "r"(a[1]), "r"(a[2]), "r"(a[3]), "r"(b0), "r"(b1));
}

// sortable-ascending float map (smallest cos first)
__device__ __forceinline__ unsigned fmap(float v) {
    unsigned u = __float_as_uint(v);
    return (u & 0x80000000u) ? ~u : (u | 0x80000000u);
}

// ---- u32 sorted small-list primitives (ascending, keep smallest) ----
__device__ __forceinline__ void insert4(unsigned (&a)[4], unsigned key) {
    if (key < a[3]) {
        a[3] = key;
        #pragma unroll
        for (int q = 3; q > 0; q--)
            if (a[q] < a[q - 1]) { unsigned t = a[q]; a[q] = a[q - 1]; a[q - 1] = t; }
    }
}
__device__ __forceinline__ void merge4(unsigned (&a)[4], const unsigned (&b)[4]) {
    #pragma unroll
    for (int q = 0; q < 4; q++) { unsigned o = b[3 - q]; if (o < a[q]) a[q] = o; }
    #pragma unroll
    for (int kk = 2; kk >= 1; kk >>= 1)
        #pragma unroll
        for (int i = 0; i < 4; i++)
            if (!(i & kk)) { int j = i | kk; if (a[j] < a[i]) { unsigned t = a[i]; a[i] = a[j]; a[j] = t; } }
}
__device__ __forceinline__ void insert16(unsigned (&a)[16], unsigned key) {
    if (key < a[15]) {
        a[15] = key;
        #pragma unroll
        for (int q = 15; q > 0; q--)
            if (a[q] < a[q - 1]) { unsigned t = a[q]; a[q] = a[q - 1]; a[q - 1] = t; }
    }
}
__device__ __forceinline__ void merge16(unsigned (&a)[16], const unsigned (&b)[16]) {
    #pragma unroll
    for (int q = 0; q < 16; q++) { unsigned o = b[15 - q]; if (o < a[q]) a[q] = o; }
    #pragma unroll
    for (int kk = 8; kk >= 1; kk >>= 1)
        #pragma unroll
        for (int i = 0; i < 16; i++)
            if (!(i & kk)) { int j = i | kk; if (a[j] < a[i]) { unsigned t = a[i]; a[i] = a[j]; a[j] = t; } }
}

// ---------------- kernel 1: per-key inverse L2 norm ----------------
__global__ void key_norm_kernel(const float* __restrict__ keys) {
    int row = blockIdx.x * blockDim.y + threadIdx.y;
    const float* kr = keys + (size_t)row * KD;
    float s = 0.f;
    for (int i = threadIdx.x; i < KD; i += 32) { float v = kr[i]; s = fmaf(v, v, s); }
    #pragma unroll
    for (int o = 16; o; o >>= 1) s += __shfl_xor_sync(0xffffffffu, s, o);
    if (threadIdx.x == 0) {
        double d = (double)fmaxf(s, 1e-12f);
        g_invk[row] = (float)(1.0 / sqrt(d));
    }
}

// ---------------- kernel 2: fp32 -> bf16 convert (row-major) ----------------
__device__ __forceinline__ unsigned pack_bf16(float a, float b) {
    __nv_bfloat16 ha = __float2bfloat16_rn(a);
    __nv_bfloat16 hb = __float2bfloat16_rn(b);
    unsigned short ua = *(unsigned short*)&ha;
    unsigned short ub = *(unsigned short*)&hb;
    return (unsigned)ua | ((unsigned)ub << 16);
}
__global__ void convert_kernel(const float* __restrict__ src, int which) {
    int i = blockIdx.x * blockDim.x + threadIdx.x;
    const float* s = src + (size_t)i * 8;
    float4 f0 = *(const float4*)s;
    float4 f1 = *(const float4*)(s + 4);
    if (which) {
        float iv = g_invk[i >> 6];
        f0.x *= iv; f0.y *= iv; f0.z *= iv; f0.w *= iv;
        f1.x *= iv; f1.y *= iv; f1.z *= iv; f1.w *= iv;
    }
    uint4 o;
    o.x = pack_bf16(f0.x, f0.y); o.y = pack_bf16(f0.z, f0.w);
    o.z = pack_bf16(f1.x, f1.y); o.w = pack_bf16(f1.z, f1.w);
    uint4* dst = which ? (uint4*)g_Kb : (uint4*)g_Xb;
    dst[i] = o;
}

// ---------------- kernel 3: coarse bf16 HMMA GEMM + fused per-tile top-4 ----
__global__ void __launch_bounds__(256) coarse_gemm() {
    __shared__ __align__(1024) char sA[STAGES][A_STAGE_BYTES];
    __shared__ __align__(1024) char sB[STAGES][B_STAGE_BYTES];
    const uint32_t aU = smem_to_u32(sA);
    const uint32_t bU = smem_to_u32(sB);
    const int t = threadIdx.x;
    const int rowbase = blockIdx.y * BM;
    const int colbase = blockIdx.x * BN;
    const __nv_bfloat16* Xb = g_Xb;
    const __nv_bfloat16* Kb = g_Kb;

    auto load_stage = [&](int st, int kt) {
        const int k0 = kt * BK;
        #pragma unroll
        for (int i = 0; i < 2; i++) {
            int ch = t + i * 256;
            int row = ch >> 2, c = ch & 3;
            int ph = c ^ ((row >> 1) & 3);
            cp16(aU + st * A_STAGE_BYTES + row * 64 + ph * 16,
                 Xb + (size_t)(rowbase + row) * KD + k0 + c * 8);
        }
        #pragma unroll
        for (int i = 0; i < 2; i++) {
            int ch = t + i * 256;
            int row = ch >> 2, c = ch & 3;
            int ph = c ^ ((row >> 1) & 3);
            cp16(bU + st * B_STAGE_BYTES + row * 64 + ph * 16,
                 Kb + (size_t)(colbase + row) * KD + k0 + c * 8);
        }
    };

    load_stage(0, 0); CP_COMMIT();
    load_stage(1, 1); CP_COMMIT();

    const int wid = t >> 5, lane = t & 31;
    const int wm = wid & 3, wn = wid >> 2;   // 4x2 warp grid: 32-row x 64-col tiles

    float acc[2][8][4];
    #pragma unroll
    for (int mt = 0; mt < 2; mt++)
        #pragma unroll
        for (int nt = 0; nt < 8; nt++)
            #pragma unroll
            for (int q = 0; q < 4; q++) acc[mt][nt][q] = 0.f;

    for (int kt = 0; kt < NKT; kt++) {
        CP_WAIT1();
        __syncthreads();
        const int nk = kt + STAGES - 1;
        if (nk < NKT) load_stage(nk % STAGES, nk);
        CP_COMMIT();

        const int st = kt % STAGES;
        const uint32_t aS = aU + st * A_STAGE_BYTES;
        const uint32_t bS = bU + st * B_STAGE_BYTES;

        #pragma unroll
        for (int s = 0; s < 2; s++) {
            uint32_t ar[2][4];
            #pragma unroll
            for (int mt = 0; mt < 2; mt++) {
                int row = wm * 32 + mt * 16 + (lane & 15);
                int cL = 2 * s + (lane >> 4);
                int ph = cL ^ ((row >> 1) & 3);
                ldm4(ar[mt], aS + row * 64 + ph * 16);
            }
            uint32_t br[4][4];
            #pragma unroll
            for (int np = 0; np < 4; np++) {
                int nrow = wn * 64 + np * 16 + (lane & 7) + ((lane >> 4) << 3);
                int cL = 2 * s + ((lane >> 3) & 1);
                int ph = cL ^ ((nrow >> 1) & 3);
                ldm4(br[np], bS + nrow * 64 + ph * 16);
            }
            #pragma unroll
            for (int mt = 0; mt < 2; mt++)
                #pragma unroll
                for (int np = 0; np < 4; np++) {
                    mma16816(acc[mt][np * 2 + 0], ar[mt], br[np][0], br[np][1]);
                    mma16816(acc[mt][np * 2 + 1], ar[mt], br[np][2], br[np][3]);
                }
        }
    }

    // ---- fused epilogue: per-row top-4 of this 128x128 tile (u32 keys) ----
    // key = (fmap(score) & ~0xFFF) | global_col  (20 score bits + 12 col bits)
    // Containment: any exact-top-4 item ranks <=4 in its tile (7-sigma margin),
    // hence <=4 within its lane's 16 values, so per-lane top-4 keeps it.
    CP_WAIT0();
    __syncthreads();
    unsigned* cbuf = (unsigned*)sA;   // [2 warp-cols][128 rows][4] u32 = 4 KB

    const int g = lane >> 2;      // row within 8-group
    const int sub = lane & 3;     // column sub-slot

    #pragma unroll
    for (int mt = 0; mt < 2; mt++) {
        #pragma unroll
        for (int h = 0; h < 2; h++) {
            unsigned a4[4];
            #pragma unroll
            for (int q = 0; q < 4; q++) a4[q] = 0xFFFFFFFFu;
            #pragma unroll
            for (int nt = 0; nt < 8; nt++) {
                #pragma unroll
                for (int j = 0; j < 2; j++) {
                    float v = acc[mt][nt][2 * h + j];
                    unsigned col = (unsigned)(colbase + wn * 64 + nt * 8 + 2 * sub + j);
                    insert4(a4, (fmap(v) & 0xFFFFF000u) | col);
                }
            }
            #pragma unroll
            for (int off = 1; off <= 2; off <<= 1) {
                unsigned b4[4];
                #pragma unroll
                for (int q = 0; q < 4; q++) b4[q] = __shfl_xor_sync(0xffffffffu, a4[q], off);
                merge4(a4, b4);
            }
            const int rloc = wm * 32 + mt * 16 + h * 8 + g;   // 0..127
            if (sub == 0) {
                #pragma unroll
                for (int q = 0; q < 4; q++) cbuf[(wn * 128 + rloc) * 4 + q] = a4[q];
            }
        }
    }
    __syncthreads();

    if (t < 128) {
        unsigned a4[4], b4[4];
        #pragma unroll
        for (int q = 0; q < 4; q++) { a4[q] = cbuf[t * 4 + q]; b4[q] = cbuf[(128 + t) * 4 + q]; }
        merge4(a4, b4);
        uint4* dst = (uint4*)(g_tilecand + ((size_t)(rowbase + t) * NTILE + blockIdx.x) * 4);
        *dst = make_uint4(a4[0], a4[1], a4[2], a4[3]);
    }
}

// ---------------- kernel 4: merge per-tile top-4 -> coarse top-16 ----------
__global__ void cand_merge_kernel() {
    const int row = blockIdx.x * 4 + (threadIdx.x >> 5);
    const int lane = threadIdx.x & 31;
    const unsigned* src = g_tilecand + (size_t)row * (NTILE * 4);
    unsigned a[16];
    #pragma unroll
    for (int q = 0; q < 16; q++) a[q] = 0xFFFFFFFFu;
    uint4 v = *(const uint4*)(src + lane * 4);   // lane <-> tile
    insert16(a, v.x); insert16(a, v.y); insert16(a, v.z); insert16(a, v.w);
    #pragma unroll
    for (int off = 16; off; off >>= 1) {
        unsigned b[16];
        #pragma unroll
        for (int q = 0; q < 16; q++) b[q] = __shfl_xor_sync(0xffffffffu, a[q], off);
        merge16(a, b);
    }
    if (lane < 16) g_cand[row * CAND + lane] = (int)(a[lane] & 0xFFFu);
}

// ---------------- kernel 5: exact fp32 rescore of 16 candidates ----------------
__global__ void rescore_kernel(const float* __restrict__ x, const float* __restrict__ keys) {
    const int row = blockIdx.x;
    __shared__ float xs[KD];
    __shared__ unsigned long long ck[CAND];
    const int tid = threadIdx.x, wid = tid >> 5, lane = tid & 31;
    *(float4*)&xs[tid * 4] = *(const float4*)(x + (size_t)row * KD + tid * 4);
    __syncthreads();
    for (int c = wid; c < CAND; c += 4) {
        const int idx = g_cand[row * CAND + c];
        const float* kr = keys + (size_t)idx * KD;
        float sum = 0.f;
        #pragma unroll
        for (int j = 0; j < 16; j++) sum = fmaf(xs[lane + 32 * j], kr[lane + 32 * j], sum);
        #pragma unroll
        for (int o = 16; o; o >>= 1) sum += __shfl_xor_sync(0xffffffffu, sum, o);
        if (lane == 0) {
            float sc = sum * g_invk[idx];
            ck[c] = ((unsigned long long)fmap(sc) << 32) | (unsigned)idx;
        }
    }
    __syncthreads();
    if (tid == 0) {
        #pragma unroll
        for (int q = 0; q < TOPK; q++) {
            unsigned long long best = ~0ull; int bi = 0;
            #pragma unroll
            for (int c = 0; c < CAND; c++) if (ck[c] < best) { best = ck[c]; bi = c; }
            ck[bi] = ~0ull;
            g_topidx[row * TOPK + q] = (int)(best & 0xffffffffu);
        }
    }
}

// ---------------- kernel 6: gather (streaming stores) ----------------
__global__ void gather_kernel(const float* __restrict__ pv, float* __restrict__ out) {
    const int b = blockIdx.x, j = blockIdx.y;
    const int idx = g_topidx[b * TOPK + j];
    const float4* src = (const float4*)(pv + (size_t)idx * ROW_ELEMS);
    float4* dst = (float4*)(out + (size_t)b * (TOPK * ROW_ELEMS) + (size_t)j * ROW_ELEMS);
    #pragma unroll 8
    for (int i = threadIdx.x; i < ROW_ELEMS / 4; i += 256)
        __stcs(dst + i, __ldg(src + i));
}

// ---------------- launcher ----------------
extern "C" void kernel_launch(void* const* d_in, const int* in_sizes, int n_in,
                              void* d_out, int out_size) {
    const float* x    = (const float*)d_in[0];   // (4096, 512)
    const float* keys = (const float*)d_in[1];   // (4096, 512)
    const float* pv   = (const float*)d_in[2];   // (4096, 16, 512)
    float* out = (float*)d_out;

    key_norm_kernel<<<NP / 8, dim3(32, 8)>>>(keys);
    convert_kernel<<<(NB * KD / 8) / 256, 256>>>(x, 0);
    convert_kernel<<<(NP * KD / 8) / 256, 256>>>(keys, 1);
    coarse_gemm<<<dim3(NP / BN, NB / BM), 256>>>();
    cand_merge_kernel<<<NB / 4, 128>>>();
    rescore_kernel<<<NB, 128>>>(x, keys);
    gather_kernel<<<dim3(NB, TOPK), 256>>>(pv, out);
}

// round 9
// speedup vs baseline: 2.6072x; 1.0357x over previous
#include <cuda_runtime.h>
#include <cuda_bf16.h>
#include <stdint.h>
#include <math.h>

// ---------------- problem constants ----------------
#define KD    512
#define TOPK  4
#define ROW_ELEMS 8192
#define NB 4096
#define NP 4096
#define CAND 16
#define NTILE (NP/128)       // 32 column tiles

// ---------------- GEMM tiling ----------------
#define BM 128
#define BN 128
#define BK 32
#define STAGES 3
#define NKT (KD/BK)          // 16 k-steps
#define A_STAGE_BYTES (BM*BK*2)   // 8192
#define B_STAGE_BYTES (BN*BK*2)   // 8192

// ---------------- device scratch ----------------
__device__ float g_invk[NP];
__device__ unsigned g_tilecand[(size_t)NB * NTILE * 4];  // 2 MB, u32 keys
__device__ int   g_topidx[NB * TOPK];
__device__ __nv_bfloat16 g_Xb[(size_t)NB * KD];      // 4 MB
__device__ __nv_bfloat16 g_Kb[(size_t)NP * KD];      // 4 MB (pre-scaled by invk)

// ---------------- helpers ----------------
__device__ __forceinline__ uint32_t smem_to_u32(const void* p) {
    uint32_t a;
    asm("{ .reg .u64 t; cvta.to.shared.u64 t, %1; cvt.u32.u64 %0, t; }" : "=r"(a) : "l"(p));
    return a;
}
__device__ __forceinline__ void cp16(uint32_t dst, const void* src) {
    asm volatile("cp.async.cg.shared.global [%0], [%1], 16;" :: "r"(dst), "l"(src) : "memory");
}
#define CP_COMMIT() asm volatile("cp.async.commit_group;" ::: "memory")
#define CP_WAIT1()  asm volatile("cp.async.wait_group 1;" ::: "memory")
#define CP_WAIT0()  asm volatile("cp.async.wait_group 0;" ::: "memory")

__device__ __forceinline__ void ldm4(uint32_t* r, uint32_t a) {
    asm volatile("ldmatrix.sync.aligned.m8n8.x4.shared.b16 {%0,%1,%2,%3}, [%4];"
                 : "=r"(r[0]), "=r"(r[1]), "=r"(r[2]), "=r"(r[3]) : "r"(a));
}
__device__ __forceinline__ void mma16816(float* c, const uint32_t* a, uint32_t b0, uint32_t b1) {
    asm volatile("mma.sync.aligned.m16n8k16.row.col.f32.bf16.bf16.f32 "
                 "{%0,%1,%2,%3}, {%4,%5,%6,%7}, {%8,%9}, {%0,%1,%2,%3};"
                 : "+f"(c[0]), "+f"(c[1]), "+f"(c[2]), "+f"(c[3])
                 : "r"(a[0]), "r"(a[1]), "r"(a[2]), "r"(a[3]), "r"(b0), "r"(b1));
}

// sortable-ascending float map (smallest cos first)
__device__ __forceinline__ unsigned fmap(float v) {
    unsigned u = __float_as_uint(v);
    return (u & 0x80000000u) ? ~u : (u | 0x80000000u);
}

// ---- u32 sorted small-list primitives (ascending, keep smallest) ----
__device__ __forceinline__ void insert4(unsigned (&a)[4], unsigned key) {
    if (key < a[3]) {
        a[3] = key;
        #pragma unroll
        for (int q = 3; q > 0; q--)
            if (a[q] < a[q - 1]) { unsigned t = a[q]; a[q] = a[q - 1]; a[q - 1] = t; }
    }
}
__device__ __forceinline__ void merge4(unsigned (&a)[4], const unsigned (&b)[4]) {
    #pragma unroll
    for (int q = 0; q < 4; q++) { unsigned o = b[3 - q]; if (o < a[q]) a[q] = o; }
    #pragma unroll
    for (int kk = 2; kk >= 1; kk >>= 1)
        #pragma unroll
        for (int i = 0; i < 4; i++)
            if (!(i & kk)) { int j = i | kk; if (a[j] < a[i]) { unsigned t = a[i]; a[i] = a[j]; a[j] = t; } }
}
__device__ __forceinline__ void insert16(unsigned (&a)[16], unsigned key) {
    if (key < a[15]) {
        a[15] = key;
        #pragma unroll
        for (int q = 15; q > 0; q--)
            if (a[q] < a[q - 1]) { unsigned t = a[q]; a[q] = a[q - 1]; a[q - 1] = t; }
    }
}
__device__ __forceinline__ void merge16(unsigned (&a)[16], const unsigned (&b)[16]) {
    #pragma unroll
    for (int q = 0; q < 16; q++) { unsigned o = b[15 - q]; if (o < a[q]) a[q] = o; }
    #pragma unroll
    for (int kk = 8; kk >= 1; kk >>= 1)
        #pragma unroll
        for (int i = 0; i < 16; i++)
            if (!(i & kk)) { int j = i | kk; if (a[j] < a[i]) { unsigned t = a[i]; a[i] = a[j]; a[j] = t; } }
}

__device__ __forceinline__ unsigned pack_bf16(float a, float b) {
    __nv_bfloat16 ha = __float2bfloat16_rn(a);
    __nv_bfloat16 hb = __float2bfloat16_rn(b);
    unsigned short ua = *(unsigned short*)&ha;
    unsigned short ub = *(unsigned short*)&hb;
    return (unsigned)ua | ((unsigned)ub << 16);
}

// ---------------- kernel 1: x fp32 -> bf16 convert ----------------
__global__ void convert_x_kernel(const float* __restrict__ src) {
    int i = blockIdx.x * blockDim.x + threadIdx.x;
    const float* s = src + (size_t)i * 8;
    float4 f0 = *(const float4*)s;
    float4 f1 = *(const float4*)(s + 4);
    uint4 o;
    o.x = pack_bf16(f0.x, f0.y); o.y = pack_bf16(f0.z, f0.w);
    o.z = pack_bf16(f1.x, f1.y); o.w = pack_bf16(f1.z, f1.w);
    ((uint4*)g_Xb)[i] = o;
}

// ---------------- kernel 2: keys fused norm + convert (warp per row) ------
__global__ void convert_keys_kernel(const float* __restrict__ keys) {
    const int wid = threadIdx.x >> 5, lane = threadIdx.x & 31;
    const int row = blockIdx.x * 8 + wid;
    const float* kr = keys + (size_t)row * KD;

    float4 v[4];
    float s = 0.f;
    #pragma unroll
    for (int c4 = 0; c4 < 4; c4++) {
        v[c4] = *(const float4*)(kr + c4 * 128 + lane * 4);
        s = fmaf(v[c4].x, v[c4].x, s);
        s = fmaf(v[c4].y, v[c4].y, s);
        s = fmaf(v[c4].z, v[c4].z, s);
        s = fmaf(v[c4].w, v[c4].w, s);
    }
    #pragma unroll
    for (int o = 16; o; o >>= 1) s += __shfl_xor_sync(0xffffffffu, s, o);
    double d = (double)fmaxf(s, 1e-12f);
    float iv = (float)(1.0 / sqrt(d));
    if (lane == 0) g_invk[row] = iv;

    uint2* dst = (uint2*)(g_Kb + (size_t)row * KD);
    #pragma unroll
    for (int c4 = 0; c4 < 4; c4++) {
        uint2 o;
        o.x = pack_bf16(v[c4].x * iv, v[c4].y * iv);
        o.y = pack_bf16(v[c4].z * iv, v[c4].w * iv);
        dst[(c4 * 128 + lane * 4) >> 2] = o;   // uint2 = 4 bf16 elements
    }
}

// ---------------- kernel 3: coarse bf16 HMMA GEMM + fused per-tile top-4 ----
__global__ void __launch_bounds__(256) coarse_gemm() {
    __shared__ __align__(1024) char sA[STAGES][A_STAGE_BYTES];
    __shared__ __align__(1024) char sB[STAGES][B_STAGE_BYTES];
    const uint32_t aU = smem_to_u32(sA);
    const uint32_t bU = smem_to_u32(sB);
    const int t = threadIdx.x;
    const int rowbase = blockIdx.y * BM;
    const int colbase = blockIdx.x * BN;
    const __nv_bfloat16* Xb = g_Xb;
    const __nv_bfloat16* Kb = g_Kb;

    auto load_stage = [&](int st, int kt) {
        const int k0 = kt * BK;
        #pragma unroll
        for (int i = 0; i < 2; i++) {
            int ch = t + i * 256;
            int row = ch >> 2, c = ch & 3;
            int ph = c ^ ((row >> 1) & 3);
            cp16(aU + st * A_STAGE_BYTES + row * 64 + ph * 16,
                 Xb + (size_t)(rowbase + row) * KD + k0 + c * 8);
        }
        #pragma unroll
        for (int i = 0; i < 2; i++) {
            int ch = t + i * 256;
            int row = ch >> 2, c = ch & 3;
            int ph = c ^ ((row >> 1) & 3);
            cp16(bU + st * B_STAGE_BYTES + row * 64 + ph * 16,
                 Kb + (size_t)(colbase + row) * KD + k0 + c * 8);
        }
    };

    load_stage(0, 0); CP_COMMIT();
    load_stage(1, 1); CP_COMMIT();

    const int wid = t >> 5, lane = t & 31;
    const int wm = wid & 3, wn = wid >> 2;   // 4x2 warp grid: 32-row x 64-col tiles

    float acc[2][8][4];
    #pragma unroll
    for (int mt = 0; mt < 2; mt++)
        #pragma unroll
        for (int nt = 0; nt < 8; nt++)
            #pragma unroll
            for (int q = 0; q < 4; q++) acc[mt][nt][q] = 0.f;

    for (int kt = 0; kt < NKT; kt++) {
        CP_WAIT1();
        __syncthreads();
        const int nk = kt + STAGES - 1;
        if (nk < NKT) load_stage(nk % STAGES, nk);
        CP_COMMIT();

        const int st = kt % STAGES;
        const uint32_t aS = aU + st * A_STAGE_BYTES;
        const uint32_t bS = bU + st * B_STAGE_BYTES;

        #pragma unroll
        for (int s = 0; s < 2; s++) {
            uint32_t ar[2][4];
            #pragma unroll
            for (int mt = 0; mt < 2; mt++) {
                int row = wm * 32 + mt * 16 + (lane & 15);
                int cL = 2 * s + (lane >> 4);
                int ph = cL ^ ((row >> 1) & 3);
                ldm4(ar[mt], aS + row * 64 + ph * 16);
            }
            uint32_t br[4][4];
            #pragma unroll
            for (int np = 0; np < 4; np++) {
                int nrow = wn * 64 + np * 16 + (lane & 7) + ((lane >> 4) << 3);
                int cL = 2 * s + ((lane >> 3) & 1);
                int ph = cL ^ ((nrow >> 1) & 3);
                ldm4(br[np], bS + nrow * 64 + ph * 16);
            }
            #pragma unroll
            for (int mt = 0; mt < 2; mt++)
                #pragma unroll
                for (int np = 0; np < 4; np++) {
                    mma16816(acc[mt][np * 2 + 0], ar[mt], br[np][0], br[np][1]);
                    mma16816(acc[mt][np * 2 + 1], ar[mt], br[np][2], br[np][3]);
                }
        }
    }

    // ---- fused epilogue: per-row top-4 of this 128x128 tile (u32 keys) ----
    // key = (fmap(score) & ~0xFFF) | global_col  (20 score bits + 12 col bits)
    CP_WAIT0();
    __syncthreads();
    unsigned* cbuf = (unsigned*)sA;   // [2 warp-cols][128 rows][4] u32 = 4 KB

    const int g = lane >> 2;      // row within 8-group
    const int sub = lane & 3;     // column sub-slot

    #pragma unroll
    for (int mt = 0; mt < 2; mt++) {
        #pragma unroll
        for (int h = 0; h < 2; h++) {
            unsigned a4[4];
            #pragma unroll
            for (int q = 0; q < 4; q++) a4[q] = 0xFFFFFFFFu;
            #pragma unroll
            for (int nt = 0; nt < 8; nt++) {
                #pragma unroll
                for (int j = 0; j < 2; j++) {
                    float v = acc[mt][nt][2 * h + j];
                    unsigned col = (unsigned)(colbase + wn * 64 + nt * 8 + 2 * sub + j);
                    insert4(a4, (fmap(v) & 0xFFFFF000u) | col);
                }
            }
            #pragma unroll
            for (int off = 1; off <= 2; off <<= 1) {
                unsigned b4[4];
                #pragma unroll
                for (int q = 0; q < 4; q++) b4[q] = __shfl_xor_sync(0xffffffffu, a4[q], off);
                merge4(a4, b4);
            }
            const int rloc = wm * 32 + mt * 16 + h * 8 + g;   // 0..127
            if (sub == 0) {
                #pragma unroll
                for (int q = 0; q < 4; q++) cbuf[(wn * 128 + rloc) * 4 + q] = a4[q];
            }
        }
    }
    __syncthreads();

    if (t < 128) {
        unsigned a4[4], b4[4];
        #pragma unroll
        for (int q = 0; q < 4; q++) { a4[q] = cbuf[t * 4 + q]; b4[q] = cbuf[(128 + t) * 4 + q]; }
        merge4(a4, b4);
        uint4* dst = (uint4*)(g_tilecand + ((size_t)(rowbase + t) * NTILE + blockIdx.x) * 4);
        *dst = make_uint4(a4[0], a4[1], a4[2], a4[3]);
    }
}

// ---------------- kernel 4: fused merge + exact fp32 rescore + top-4 ------
__global__ void select_kernel(const float* __restrict__ x, const float* __restrict__ keys) {
    const int row = blockIdx.x;
    __shared__ float xs[KD];
    __shared__ int cidx[CAND];
    __shared__ unsigned long long ck[CAND];
    const int tid = threadIdx.x, wid = tid >> 5, lane = tid & 31;

    *(float4*)&xs[tid * 4] = *(const float4*)(x + (size_t)row * KD + tid * 4);

    if (wid == 0) {
        // merge 32 tiles x 4 keys -> coarse top-16
        unsigned a[16];
        #pragma unroll
        for (int q = 0; q < 16; q++) a[q] = 0xFFFFFFFFu;
        uint4 v = *(const uint4*)(g_tilecand + ((size_t)row * NTILE + lane) * 4);
        insert16(a, v.x); insert16(a, v.y); insert16(a, v.z); insert16(a, v.w);
        #pragma unroll
        for (int off = 16; off; off >>= 1) {
            unsigned b[16];
            #pragma unroll
            for (int q = 0; q < 16; q++) b[q] = __shfl_xor_sync(0xffffffffu, a[q], off);
            merge16(a, b);
        }
        if (lane < 16) cidx[lane] = (int)(a[lane] & 0xFFFu);
    }
    __syncthreads();

    for (int c = wid; c < CAND; c += 4) {
        const int idx = cidx[c];
        const float* kr = keys + (size_t)idx * KD;
        float sum = 0.f;
        #pragma unroll
        for (int j = 0; j < 16; j++) sum = fmaf(xs[lane + 32 * j], kr[lane + 32 * j], sum);
        #pragma unroll
        for (int o = 16; o; o >>= 1) sum += __shfl_xor_sync(0xffffffffu, sum, o);
        if (lane == 0) {
            float sc = sum * g_invk[idx];
            ck[c] = ((unsigned long long)fmap(sc) << 32) | (unsigned)idx;
        }
    }
    __syncthreads();
    if (tid == 0) {
        #pragma unroll
        for (int q = 0; q < TOPK; q++) {
            unsigned long long best = ~0ull; int bi = 0;
            #pragma unroll
            for (int c = 0; c < CAND; c++) if (ck[c] < best) { best = ck[c]; bi = c; }
            ck[bi] = ~0ull;
            g_topidx[row * TOPK + q] = (int)(best & 0xffffffffu);
        }
    }
}

// ---------------- kernel 5: gather (streaming stores) ----------------
__global__ void gather_kernel(const float* __restrict__ pv, float* __restrict__ out) {
    const int b = blockIdx.x, j = blockIdx.y;
    const int idx = g_topidx[b * TOPK + j];
    const float4* src = (const float4*)(pv + (size_t)idx * ROW_ELEMS);
    float4* dst = (float4*)(out + (size_t)b * (TOPK * ROW_ELEMS) + (size_t)j * ROW_ELEMS);
    #pragma unroll 8
    for (int i = threadIdx.x; i < ROW_ELEMS / 4; i += 256)
        __stcs(dst + i, __ldg(src + i));
}

// ---------------- launcher ----------------
extern "C" void kernel_launch(void* const* d_in, const int* in_sizes, int n_in,
                              void* d_out, int out_size) {
    const float* x    = (const float*)d_in[0];   // (4096, 512)
    const float* keys = (const float*)d_in[1];   // (4096, 512)
    const float* pv   = (const float*)d_in[2];   // (4096, 16, 512)
    float* out = (float*)d_out;

    convert_x_kernel<<<(NB * KD / 8) / 256, 256>>>(x);
    convert_keys_kernel<<<NP / 8, 256>>>(keys);
    coarse_gemm<<<dim3(NP / BN, NB / BM), 256>>>();
    select_kernel<<<NB, 128>>>(x, keys);
    gather_kernel<<<dim3(NB, TOPK), 256>>>(pv, out);
}

// round 10
// speedup vs baseline: 2.6742x; 1.0257x over previous
#include <cuda_runtime.h>
#include <cuda_bf16.h>
#include <stdint.h>
#include <math.h>

// ---------------- problem constants ----------------
#define KD    512
#define TOPK  4
#define ROW_ELEMS 8192
#define NB 4096
#define NP 4096
#define CAND 16
#define NTILE (NP/128)       // 32 column tiles

// ---------------- GEMM tiling ----------------
#define BM 128
#define BN 128
#define BK 32
#define STAGES 3
#define NKT (KD/BK)          // 16 k-steps
#define A_STAGE_BYTES (BM*BK*2)   // 8192
#define B_STAGE_BYTES (BN*BK*2)   // 8192

// ---------------- device scratch ----------------
__device__ float g_invk[NP];
__device__ unsigned g_tilecand[(size_t)NB * NTILE * 4];  // 2 MB, u32 keys
__device__ int   g_topidx[NB * TOPK];
__device__ __nv_bfloat16 g_Xb[(size_t)NB * KD];      // 4 MB
__device__ __nv_bfloat16 g_Kb[(size_t)NP * KD];      // 4 MB (pre-scaled by invk)

// ---------------- helpers ----------------
__device__ __forceinline__ uint32_t smem_to_u32(const void* p) {
    uint32_t a;
    asm("{ .reg .u64 t; cvta.to.shared.u64 t, %1; cvt.u32.u64 %0, t; }" : "=r"(a) : "l"(p));
    return a;
}
__device__ __forceinline__ void cp16(uint32_t dst, const void* src) {
    asm volatile("cp.async.cg.shared.global [%0], [%1], 16;" :: "r"(dst), "l"(src) : "memory");
}
#define CP_COMMIT() asm volatile("cp.async.commit_group;" ::: "memory")
#define CP_WAIT1()  asm volatile("cp.async.wait_group 1;" ::: "memory")
#define CP_WAIT0()  asm volatile("cp.async.wait_group 0;" ::: "memory")

__device__ __forceinline__ void ldm4(uint32_t* r, uint32_t a) {
    asm volatile("ldmatrix.sync.aligned.m8n8.x4.shared.b16 {%0,%1,%2,%3}, [%4];"
                 : "=r"(r[0]), "=r"(r[1]), "=r"(r[2]), "=r"(r[3]) : "r"(a));
}
__device__ __forceinline__ void mma16816(float* c, const uint32_t* a, uint32_t b0, uint32_t b1) {
    asm volatile("mma.sync.aligned.m16n8k16.row.col.f32.bf16.bf16.f32 "
                 "{%0,%1,%2,%3}, {%4,%5,%6,%7}, {%8,%9}, {%0,%1,%2,%3};"
                 : "+f"(c[0]), "+f"(c[1]), "+f"(c[2]), "+f"(c[3])
                 : "r"(a[0]), "r"(a[1]), "r"(a[2]), "r"(a[3]), "r"(b0), "r"(b1));
}

// sortable-ascending float map (smallest cos first)
__device__ __forceinline__ unsigned fmap(float v) {
    unsigned u = __float_as_uint(v);
    return (u & 0x80000000u) ? ~u : (u | 0x80000000u);
}

// ---- u32 sorted small-list primitives (ascending, keep smallest) ----
__device__ __forceinline__ void insert4(unsigned (&a)[4], unsigned key) {
    if (key < a[3]) {
        a[3] = key;
        #pragma unroll
        for (int q = 3; q > 0; q--)
            if (a[q] < a[q - 1]) { unsigned t = a[q]; a[q] = a[q - 1]; a[q - 1] = t; }
    }
}
__device__ __forceinline__ void merge4(unsigned (&a)[4], const unsigned (&b)[4]) {
    #pragma unroll
    for (int q = 0; q < 4; q++) { unsigned o = b[3 - q]; if (o < a[q]) a[q] = o; }
    #pragma unroll
    for (int kk = 2; kk >= 1; kk >>= 1)
        #pragma unroll
        for (int i = 0; i < 4; i++)
            if (!(i & kk)) { int j = i | kk; if (a[j] < a[i]) { unsigned t = a[i]; a[i] = a[j]; a[j] = t; } }
}
__device__ __forceinline__ void insert16(unsigned (&a)[16], unsigned key) {
    if (key < a[15]) {
        a[15] = key;
        #pragma unroll
        for (int q = 15; q > 0; q--)
            if (a[q] < a[q - 1]) { unsigned t = a[q]; a[q] = a[q - 1]; a[q - 1] = t; }
    }
}
__device__ __forceinline__ void merge16(unsigned (&a)[16], const unsigned (&b)[16]) {
    #pragma unroll
    for (int q = 0; q < 16; q++) { unsigned o = b[15 - q]; if (o < a[q]) a[q] = o; }
    #pragma unroll
    for (int kk = 8; kk >= 1; kk >>= 1)
        #pragma unroll
        for (int i = 0; i < 16; i++)
            if (!(i & kk)) { int j = i | kk; if (a[j] < a[i]) { unsigned t = a[i]; a[i] = a[j]; a[j] = t; } }
}

__device__ __forceinline__ unsigned pack_bf16(float a, float b) {
    __nv_bfloat16 ha = __float2bfloat16_rn(a);
    __nv_bfloat16 hb = __float2bfloat16_rn(b);
    unsigned short ua = *(unsigned short*)&ha;
    unsigned short ub = *(unsigned short*)&hb;
    return (unsigned)ua | ((unsigned)ub << 16);
}

// ---------------- kernel 1: fused converts (x part + keys part) -----------
// blocks [0, 1024): x fp32->bf16.  blocks [1024, 1536): keys norm+convert.
__global__ void convert_all_kernel(const float* __restrict__ x, const float* __restrict__ keys) {
    if (blockIdx.x < 1024) {
        int i = blockIdx.x * 256 + threadIdx.x;
        const float* s = x + (size_t)i * 8;
        float4 f0 = *(const float4*)s;
        float4 f1 = *(const float4*)(s + 4);
        uint4 o;
        o.x = pack_bf16(f0.x, f0.y); o.y = pack_bf16(f0.z, f0.w);
        o.z = pack_bf16(f1.x, f1.y); o.w = pack_bf16(f1.z, f1.w);
        ((uint4*)g_Xb)[i] = o;
    } else {
        const int wid = threadIdx.x >> 5, lane = threadIdx.x & 31;
        const int row = (blockIdx.x - 1024) * 8 + wid;
        const float* kr = keys + (size_t)row * KD;
        float4 v[4];
        float s = 0.f;
        #pragma unroll
        for (int c4 = 0; c4 < 4; c4++) {
            v[c4] = *(const float4*)(kr + c4 * 128 + lane * 4);
            s = fmaf(v[c4].x, v[c4].x, s);
            s = fmaf(v[c4].y, v[c4].y, s);
            s = fmaf(v[c4].z, v[c4].z, s);
            s = fmaf(v[c4].w, v[c4].w, s);
        }
        #pragma unroll
        for (int o = 16; o; o >>= 1) s += __shfl_xor_sync(0xffffffffu, s, o);
        double d = (double)fmaxf(s, 1e-12f);
        float iv = (float)(1.0 / sqrt(d));
        if (lane == 0) g_invk[row] = iv;
        uint2* dst = (uint2*)(g_Kb + (size_t)row * KD);
        #pragma unroll
        for (int c4 = 0; c4 < 4; c4++) {
            uint2 o;
            o.x = pack_bf16(v[c4].x * iv, v[c4].y * iv);
            o.y = pack_bf16(v[c4].z * iv, v[c4].w * iv);
            dst[(c4 * 128 + lane * 4) >> 2] = o;
        }
    }
}

// ---------------- kernel 2: coarse bf16 HMMA GEMM + fused per-tile top-4 ----
__global__ void __launch_bounds__(256) coarse_gemm() {
    __shared__ __align__(1024) char sA[STAGES][A_STAGE_BYTES];
    __shared__ __align__(1024) char sB[STAGES][B_STAGE_BYTES];
    const uint32_t aU = smem_to_u32(sA);
    const uint32_t bU = smem_to_u32(sB);
    const int t = threadIdx.x;
    const int rowbase = blockIdx.y * BM;
    const int colbase = blockIdx.x * BN;

    // ---- precomputed load-stage addressing (per thread, stage-independent) ----
    // chunk0 = t, chunk1 = t + 256 ; row = ch>>2, c = ch&3, ph = c ^ ((row>>1)&3)
    const int r0 = t >> 2, c0 = t & 3;
    const int r1 = (t + 256) >> 2, c1 = (t + 256) & 3;
    const uint32_t sOffA0 = r0 * 64 + (c0 ^ ((r0 >> 1) & 3)) * 16;
    const uint32_t sOffA1 = r1 * 64 + (c1 ^ ((r1 >> 1) & 3)) * 16;
    const __nv_bfloat16* gA0 = g_Xb + (size_t)(rowbase + r0) * KD + c0 * 8;
    const __nv_bfloat16* gA1 = g_Xb + (size_t)(rowbase + r1) * KD + c1 * 8;
    const __nv_bfloat16* gB0 = g_Kb + (size_t)(colbase + r0) * KD + c0 * 8;
    const __nv_bfloat16* gB1 = g_Kb + (size_t)(colbase + r1) * KD + c1 * 8;

    const int wid = t >> 5, lane = t & 31;
    const int wm = wid & 3, wn = wid >> 2;   // 4x2 warp grid: 32-row x 64-col tiles

    // ---- precomputed ldmatrix smem offsets (stage-independent) ----
    uint32_t offA[2][2];   // [s][mt]
    uint32_t offB[2][4];   // [s][np]
    #pragma unroll
    for (int s = 0; s < 2; s++) {
        #pragma unroll
        for (int mt = 0; mt < 2; mt++) {
            int row = wm * 32 + mt * 16 + (lane & 15);
            int cL = 2 * s + (lane >> 4);
            offA[s][mt] = row * 64 + (cL ^ ((row >> 1) & 3)) * 16;
        }
        #pragma unroll
        for (int np = 0; np < 4; np++) {
            int nrow = wn * 64 + np * 16 + (lane & 7) + ((lane >> 4) << 3);
            int cL = 2 * s + ((lane >> 3) & 1);
            offB[s][np] = nrow * 64 + (cL ^ ((nrow >> 1) & 3)) * 16;
        }
    }

    auto load_stage = [&](int st, int kt) {
        const int k0 = kt * BK;
        cp16(aU + st * A_STAGE_BYTES + sOffA0, gA0 + k0);
        cp16(aU + st * A_STAGE_BYTES + sOffA1, gA1 + k0);
        cp16(bU + st * B_STAGE_BYTES + sOffA0, gB0 + k0);
        cp16(bU + st * B_STAGE_BYTES + sOffA1, gB1 + k0);
    };

    load_stage(0, 0); CP_COMMIT();
    load_stage(1, 1); CP_COMMIT();

    float acc[2][8][4];
    #pragma unroll
    for (int mt = 0; mt < 2; mt++)
        #pragma unroll
        for (int nt = 0; nt < 8; nt++)
            #pragma unroll
            for (int q = 0; q < 4; q++) acc[mt][nt][q] = 0.f;

    int st = 0, stLoad = 2;    // rolling stage counters
    for (int kt = 0; kt < NKT; kt++) {
        CP_WAIT1();
        __syncthreads();
        const int nk = kt + STAGES - 1;
        if (nk < NKT) load_stage(stLoad, nk);
        CP_COMMIT();

        const uint32_t aS = aU + st * A_STAGE_BYTES;
        const uint32_t bS = bU + st * B_STAGE_BYTES;

        #pragma unroll
        for (int s = 0; s < 2; s++) {
            uint32_t ar[2][4];
            #pragma unroll
            for (int mt = 0; mt < 2; mt++) ldm4(ar[mt], aS + offA[s][mt]);
            uint32_t br[4][4];
            #pragma unroll
            for (int np = 0; np < 4; np++) ldm4(br[np], bS + offB[s][np]);
            #pragma unroll
            for (int mt = 0; mt < 2; mt++)
                #pragma unroll
                for (int np = 0; np < 4; np++) {
                    mma16816(acc[mt][np * 2 + 0], ar[mt], br[np][0], br[np][1]);
                    mma16816(acc[mt][np * 2 + 1], ar[mt], br[np][2], br[np][3]);
                }
        }
        st = (st == STAGES - 1) ? 0 : st + 1;
        stLoad = (stLoad == STAGES - 1) ? 0 : stLoad + 1;
    }

    // ---- fused epilogue: per-row top-4 of this 128x128 tile (u32 keys) ----
    CP_WAIT0();
    __syncthreads();
    unsigned* cbuf = (unsigned*)sA;   // [2 warp-cols][128 rows][4] u32 = 4 KB

    const int g = lane >> 2;      // row within 8-group
    const int sub = lane & 3;     // column sub-slot

    #pragma unroll
    for (int mt = 0; mt < 2; mt++) {
        #pragma unroll
        for (int h = 0; h < 2; h++) {
            unsigned a4[4];
            #pragma unroll
            for (int q = 0; q < 4; q++) a4[q] = 0xFFFFFFFFu;
            #pragma unroll
            for (int nt = 0; nt < 8; nt++) {
                #pragma unroll
                for (int j = 0; j < 2; j++) {
                    float v = acc[mt][nt][2 * h + j];
                    unsigned col = (unsigned)(colbase + wn * 64 + nt * 8 + 2 * sub + j);
                    insert4(a4, (fmap(v) & 0xFFFFF000u) | col);
                }
            }
            #pragma unroll
            for (int off = 1; off <= 2; off <<= 1) {
                unsigned b4[4];
                #pragma unroll
                for (int q = 0; q < 4; q++) b4[q] = __shfl_xor_sync(0xffffffffu, a4[q], off);
                merge4(a4, b4);
            }
            const int rloc = wm * 32 + mt * 16 + h * 8 + g;   // 0..127
            if (sub == 0) {
                #pragma unroll
                for (int q = 0; q < 4; q++) cbuf[(wn * 128 + rloc) * 4 + q] = a4[q];
            }
        }
    }
    __syncthreads();

    if (t < 128) {
        unsigned a4[4], b4[4];
        #pragma unroll
        for (int q = 0; q < 4; q++) { a4[q] = cbuf[t * 4 + q]; b4[q] = cbuf[(128 + t) * 4 + q]; }
        merge4(a4, b4);
        uint4* dst = (uint4*)(g_tilecand + ((size_t)(rowbase + t) * NTILE + blockIdx.x) * 4);
        *dst = make_uint4(a4[0], a4[1], a4[2], a4[3]);
    }
}

// ---------------- kernel 3: fused merge + exact fp32 rescore + top-4 ------
__global__ void select_kernel(const float* __restrict__ x, const float* __restrict__ keys) {
    const int row = blockIdx.x;
    __shared__ float xs[KD];
    __shared__ int cidx[CAND];
    __shared__ unsigned long long ck[CAND];
    const int tid = threadIdx.x, wid = tid >> 5, lane = tid & 31;

    *(float4*)&xs[tid * 4] = *(const float4*)(x + (size_t)row * KD + tid * 4);

    if (wid == 0) {
        unsigned a[16];
        #pragma unroll
        for (int q = 0; q < 16; q++) a[q] = 0xFFFFFFFFu;
        uint4 v = *(const uint4*)(g_tilecand + ((size_t)row * NTILE + lane) * 4);
        insert16(a, v.x); insert16(a, v.y); insert16(a, v.z); insert16(a, v.w);
        #pragma unroll
        for (int off = 16; off; off >>= 1) {
            unsigned b[16];
            #pragma unroll
            for (int q = 0; q < 16; q++) b[q] = __shfl_xor_sync(0xffffffffu, a[q], off);
            merge16(a, b);
        }
        if (lane < 16) cidx[lane] = (int)(a[lane] & 0xFFFu);
    }
    __syncthreads();

    for (int c = wid; c < CAND; c += 4) {
        const int idx = cidx[c];
        const float* kr = keys + (size_t)idx * KD;
        float sum = 0.f;
        #pragma unroll
        for (int j = 0; j < 16; j++) sum = fmaf(xs[lane + 32 * j], kr[lane + 32 * j], sum);
        #pragma unroll
        for (int o = 16; o; o >>= 1) sum += __shfl_xor_sync(0xffffffffu, sum, o);
        if (lane == 0) {
            float sc = sum * g_invk[idx];
            ck[c] = ((unsigned long long)fmap(sc) << 32) | (unsigned)idx;
        }
    }
    __syncthreads();
    if (tid == 0) {
        #pragma unroll
        for (int q = 0; q < TOPK; q++) {
            unsigned long long best = ~0ull; int bi = 0;
            #pragma unroll
            for (int c = 0; c < CAND; c++) if (ck[c] < best) { best = ck[c]; bi = c; }
            ck[bi] = ~0ull;
            g_topidx[row * TOPK + q] = (int)(best & 0xffffffffu);
        }
    }
}

// ---------------- kernel 4: gather (streaming stores) ----------------
__global__ void gather_kernel(const float* __restrict__ pv, float* __restrict__ out) {
    const int b = blockIdx.x, j = blockIdx.y;
    const int idx = g_topidx[b * TOPK + j];
    const float4* src = (const float4*)(pv + (size_t)idx * ROW_ELEMS);
    float4* dst = (float4*)(out + (size_t)b * (TOPK * ROW_ELEMS) + (size_t)j * ROW_ELEMS);
    #pragma unroll 8
    for (int i = threadIdx.x; i < ROW_ELEMS / 4; i += 256)
        __stcs(dst + i, __ldg(src + i));
}

// ---------------- launcher ----------------
extern "C" void kernel_launch(void* const* d_in, const int* in_sizes, int n_in,
                              void* d_out, int out_size) {
    const float* x    = (const float*)d_in[0];   // (4096, 512)
    const float* keys = (const float*)d_in[1];   // (4096, 512)
    const float* pv   = (const float*)d_in[2];   // (4096, 16, 512)
    float* out = (float*)d_out;

    convert_all_kernel<<<1024 + NP / 8, 256>>>(x, keys);
    coarse_gemm<<<dim3(NP / BN, NB / BM), 256>>>();
    select_kernel<<<NB, 128>>>(x, keys);
    gather_kernel<<<dim3(NB, TOPK), 256>>>(pv, out);
}

// round 11
// speedup vs baseline: 2.9839x; 1.1158x over previous
#include <cuda_runtime.h>
#include <cuda_bf16.h>
#include <stdint.h>
#include <math.h>

// ---------------- problem constants ----------------
#define KD    512
#define TOPK  4
#define ROW_ELEMS 8192
#define NB 4096
#define NP 4096
#define CAND 16
#define NTILE (NP/128)       // 32 column tiles
#define NWORK (NB*TOPK)      // 16384 gather work items

// ---------------- GEMM tiling ----------------
#define BM 128
#define BN 128
#define BK 32
#define STAGES 3
#define NKT (KD/BK)          // 16 k-steps
#define A_STAGE_BYTES (BM*BK*2)   // 8192
#define B_STAGE_BYTES (BN*BK*2)   // 8192

// ---------------- device scratch ----------------
__device__ float g_invk[NP];
__device__ unsigned g_tilecand[(size_t)NB * NTILE * 4];  // 2 MB, u32 keys
__device__ int   g_topidx[NWORK];
__device__ int   g_binCount[NP];
__device__ int   g_binStart[NP];
__device__ int   g_order[NWORK];
__device__ __nv_bfloat16 g_Xb[(size_t)NB * KD];      // 4 MB
__device__ __nv_bfloat16 g_Kb[(size_t)NP * KD];      // 4 MB (pre-scaled by invk)

// ---------------- helpers ----------------
__device__ __forceinline__ uint32_t smem_to_u32(const void* p) {
    uint32_t a;
    asm("{ .reg .u64 t; cvta.to.shared.u64 t, %1; cvt.u32.u64 %0, t; }" : "=r"(a) : "l"(p));
    return a;
}
__device__ __forceinline__ void cp16(uint32_t dst, const void* src) {
    asm volatile("cp.async.cg.shared.global [%0], [%1], 16;" :: "r"(dst), "l"(src) : "memory");
}
#define CP_COMMIT() asm volatile("cp.async.commit_group;" ::: "memory")
#define CP_WAIT1()  asm volatile("cp.async.wait_group 1;" ::: "memory")
#define CP_WAIT0()  asm volatile("cp.async.wait_group 0;" ::: "memory")

__device__ __forceinline__ void ldm4(uint32_t* r, uint32_t a) {
    asm volatile("ldmatrix.sync.aligned.m8n8.x4.shared.b16 {%0,%1,%2,%3}, [%4];"
                 : "=r"(r[0]), "=r"(r[1]), "=r"(r[2]), "=r"(r[3]) : "r"(a));
}
__device__ __forceinline__ void mma16816(float* c, const uint32_t* a, uint32_t b0, uint32_t b1) {
    asm volatile("mma.sync.aligned.m16n8k16.row.col.f32.bf16.bf16.f32 "
                 "{%0,%1,%2,%3}, {%4,%5,%6,%7}, {%8,%9}, {%0,%1,%2,%3};"
                 : "+f"(c[0]), "+f"(c[1]), "+f"(c[2]), "+f"(c[3])
                 : "r"(a[0]), "r"(a[1]), "r"(a[2]), "r"(a[3]), "r"(b0), "r"(b1));
}

// sortable-ascending float map (smallest cos first)
__device__ __forceinline__ unsigned fmap(float v) {
    unsigned u = __float_as_uint(v);
    return (u & 0x80000000u) ? ~u : (u | 0x80000000u);
}

// ---- u32 sorted small-list primitives (ascending, keep smallest) ----
__device__ __forceinline__ void insert4(unsigned (&a)[4], unsigned key) {
    if (key < a[3]) {
        a[3] = key;
        #pragma unroll
        for (int q = 3; q > 0; q--)
            if (a[q] < a[q - 1]) { unsigned t = a[q]; a[q] = a[q - 1]; a[q - 1] = t; }
    }
}
__device__ __forceinline__ void merge4(unsigned (&a)[4], const unsigned (&b)[4]) {
    #pragma unroll
    for (int q = 0; q < 4; q++) { unsigned o = b[3 - q]; if (o < a[q]) a[q] = o; }
    #pragma unroll
    for (int kk = 2; kk >= 1; kk >>= 1)
        #pragma unroll
        for (int i = 0; i < 4; i++)
            if (!(i & kk)) { int j = i | kk; if (a[j] < a[i]) { unsigned t = a[i]; a[i] = a[j]; a[j] = t; } }
}
__device__ __forceinline__ void insert16(unsigned (&a)[16], unsigned key) {
    if (key < a[15]) {
        a[15] = key;
        #pragma unroll
        for (int q = 15; q > 0; q--)
            if (a[q] < a[q - 1]) { unsigned t = a[q]; a[q] = a[q - 1]; a[q - 1] = t; }
    }
}
__device__ __forceinline__ void merge16(unsigned (&a)[16], const unsigned (&b)[16]) {
    #pragma unroll
    for (int q = 0; q < 16; q++) { unsigned o = b[15 - q]; if (o < a[q]) a[q] = o; }
    #pragma unroll
    for (int kk = 8; kk >= 1; kk >>= 1)
        #pragma unroll
        for (int i = 0; i < 16; i++)
            if (!(i & kk)) { int j = i | kk; if (a[j] < a[i]) { unsigned t = a[i]; a[i] = a[j]; a[j] = t; } }
}

__device__ __forceinline__ unsigned pack_bf16(float a, float b) {
    __nv_bfloat16 ha = __float2bfloat16_rn(a);
    __nv_bfloat16 hb = __float2bfloat16_rn(b);
    unsigned short ua = *(unsigned short*)&ha;
    unsigned short ub = *(unsigned short*)&hb;
    return (unsigned)ua | ((unsigned)ub << 16);
}

// ---------------- kernel 1: fused converts + histogram zero --------------
// blocks [0,1024): x convert. [1024,1536): keys norm+convert. [1536,1552): zero bins.
__global__ void convert_all_kernel(const float* __restrict__ x, const float* __restrict__ keys) {
    if (blockIdx.x < 1024) {
        int i = blockIdx.x * 256 + threadIdx.x;
        const float* s = x + (size_t)i * 8;
        float4 f0 = *(const float4*)s;
        float4 f1 = *(const float4*)(s + 4);
        uint4 o;
        o.x = pack_bf16(f0.x, f0.y); o.y = pack_bf16(f0.z, f0.w);
        o.z = pack_bf16(f1.x, f1.y); o.w = pack_bf16(f1.z, f1.w);
        ((uint4*)g_Xb)[i] = o;
    } else if (blockIdx.x < 1536) {
        const int wid = threadIdx.x >> 5, lane = threadIdx.x & 31;
        const int row = (blockIdx.x - 1024) * 8 + wid;
        const float* kr = keys + (size_t)row * KD;
        float4 v[4];
        float s = 0.f;
        #pragma unroll
        for (int c4 = 0; c4 < 4; c4++) {
            v[c4] = *(const float4*)(kr + c4 * 128 + lane * 4);
            s = fmaf(v[c4].x, v[c4].x, s);
            s = fmaf(v[c4].y, v[c4].y, s);
            s = fmaf(v[c4].z, v[c4].z, s);
            s = fmaf(v[c4].w, v[c4].w, s);
        }
        #pragma unroll
        for (int o = 16; o; o >>= 1) s += __shfl_xor_sync(0xffffffffu, s, o);
        double d = (double)fmaxf(s, 1e-12f);
        float iv = (float)(1.0 / sqrt(d));
        if (lane == 0) g_invk[row] = iv;
        uint2* dst = (uint2*)(g_Kb + (size_t)row * KD);
        #pragma unroll
        for (int c4 = 0; c4 < 4; c4++) {
            uint2 o;
            o.x = pack_bf16(v[c4].x * iv, v[c4].y * iv);
            o.y = pack_bf16(v[c4].z * iv, v[c4].w * iv);
            dst[(c4 * 128 + lane * 4) >> 2] = o;
        }
    } else {
        int i = (blockIdx.x - 1536) * 256 + threadIdx.x;
        if (i < NP) g_binCount[i] = 0;
    }
}

// ---------------- kernel 2: coarse bf16 HMMA GEMM + fused per-tile top-4 ----
__global__ void __launch_bounds__(256) coarse_gemm() {
    __shared__ __align__(1024) char sA[STAGES][A_STAGE_BYTES];
    __shared__ __align__(1024) char sB[STAGES][B_STAGE_BYTES];
    const uint32_t aU = smem_to_u32(sA);
    const uint32_t bU = smem_to_u32(sB);
    const int t = threadIdx.x;
    const int rowbase = blockIdx.y * BM;
    const int colbase = blockIdx.x * BN;

    const int r0 = t >> 2, c0 = t & 3;
    const int r1 = (t + 256) >> 2, c1 = (t + 256) & 3;
    const uint32_t sOffA0 = r0 * 64 + (c0 ^ ((r0 >> 1) & 3)) * 16;
    const uint32_t sOffA1 = r1 * 64 + (c1 ^ ((r1 >> 1) & 3)) * 16;
    const __nv_bfloat16* gA0 = g_Xb + (size_t)(rowbase + r0) * KD + c0 * 8;
    const __nv_bfloat16* gA1 = g_Xb + (size_t)(rowbase + r1) * KD + c1 * 8;
    const __nv_bfloat16* gB0 = g_Kb + (size_t)(colbase + r0) * KD + c0 * 8;
    const __nv_bfloat16* gB1 = g_Kb + (size_t)(colbase + r1) * KD + c1 * 8;

    const int wid = t >> 5, lane = t & 31;
    const int wm = wid & 3, wn = wid >> 2;

    uint32_t offA[2][2];
    uint32_t offB[2][4];
    #pragma unroll
    for (int s = 0; s < 2; s++) {
        #pragma unroll
        for (int mt = 0; mt < 2; mt++) {
            int row = wm * 32 + mt * 16 + (lane & 15);
            int cL = 2 * s + (lane >> 4);
            offA[s][mt] = row * 64 + (cL ^ ((row >> 1) & 3)) * 16;
        }
        #pragma unroll
        for (int np = 0; np < 4; np++) {
            int nrow = wn * 64 + np * 16 + (lane & 7) + ((lane >> 4) << 3);
            int cL = 2 * s + ((lane >> 3) & 1);
            offB[s][np] = nrow * 64 + (cL ^ ((nrow >> 1) & 3)) * 16;
        }
    }

    auto load_stage = [&](int st, int kt) {
        const int k0 = kt * BK;
        cp16(aU + st * A_STAGE_BYTES + sOffA0, gA0 + k0);
        cp16(aU + st * A_STAGE_BYTES + sOffA1, gA1 + k0);
        cp16(bU + st * B_STAGE_BYTES + sOffA0, gB0 + k0);
        cp16(bU + st * B_STAGE_BYTES + sOffA1, gB1 + k0);
    };

    load_stage(0, 0); CP_COMMIT();
    load_stage(1, 1); CP_COMMIT();

    float acc[2][8][4];
    #pragma unroll
    for (int mt = 0; mt < 2; mt++)
        #pragma unroll
        for (int nt = 0; nt < 8; nt++)
            #pragma unroll
            for (int q = 0; q < 4; q++) acc[mt][nt][q] = 0.f;

    int st = 0, stLoad = 2;
    for (int kt = 0; kt < NKT; kt++) {
        CP_WAIT1();
        __syncthreads();
        const int nk = kt + STAGES - 1;
        if (nk < NKT) load_stage(stLoad, nk);
        CP_COMMIT();

        const uint32_t aS = aU + st * A_STAGE_BYTES;
        const uint32_t bS = bU + st * B_STAGE_BYTES;

        #pragma unroll
        for (int s = 0; s < 2; s++) {
            uint32_t ar[2][4];
            #pragma unroll
            for (int mt = 0; mt < 2; mt++) ldm4(ar[mt], aS + offA[s][mt]);
            uint32_t br[4][4];
            #pragma unroll
            for (int np = 0; np < 4; np++) ldm4(br[np], bS + offB[s][np]);
            #pragma unroll
            for (int mt = 0; mt < 2; mt++)
                #pragma unroll
                for (int np = 0; np < 4; np++) {
                    mma16816(acc[mt][np * 2 + 0], ar[mt], br[np][0], br[np][1]);
                    mma16816(acc[mt][np * 2 + 1], ar[mt], br[np][2], br[np][3]);
                }
        }
        st = (st == STAGES - 1) ? 0 : st + 1;
        stLoad = (stLoad == STAGES - 1) ? 0 : stLoad + 1;
    }

    CP_WAIT0();
    __syncthreads();
    unsigned* cbuf = (unsigned*)sA;

    const int g = lane >> 2;
    const int sub = lane & 3;

    #pragma unroll
    for (int mt = 0; mt < 2; mt++) {
        #pragma unroll
        for (int h = 0; h < 2; h++) {
            unsigned a4[4];
            #pragma unroll
            for (int q = 0; q < 4; q++) a4[q] = 0xFFFFFFFFu;
            #pragma unroll
            for (int nt = 0; nt < 8; nt++) {
                #pragma unroll
                for (int j = 0; j < 2; j++) {
                    float v = acc[mt][nt][2 * h + j];
                    unsigned col = (unsigned)(colbase + wn * 64 + nt * 8 + 2 * sub + j);
                    insert4(a4, (fmap(v) & 0xFFFFF000u) | col);
                }
            }
            #pragma unroll
            for (int off = 1; off <= 2; off <<= 1) {
                unsigned b4[4];
                #pragma unroll
                for (int q = 0; q < 4; q++) b4[q] = __shfl_xor_sync(0xffffffffu, a4[q], off);
                merge4(a4, b4);
            }
            const int rloc = wm * 32 + mt * 16 + h * 8 + g;
            if (sub == 0) {
                #pragma unroll
                for (int q = 0; q < 4; q++) cbuf[(wn * 128 + rloc) * 4 + q] = a4[q];
            }
        }
    }
    __syncthreads();

    if (t < 128) {
        unsigned a4[4], b4[4];
        #pragma unroll
        for (int q = 0; q < 4; q++) { a4[q] = cbuf[t * 4 + q]; b4[q] = cbuf[(128 + t) * 4 + q]; }
        merge4(a4, b4);
        uint4* dst = (uint4*)(g_tilecand + ((size_t)(rowbase + t) * NTILE + blockIdx.x) * 4);
        *dst = make_uint4(a4[0], a4[1], a4[2], a4[3]);
    }
}

// ---------------- kernel 3: merge + exact rescore + top-4 + histogram -----
__global__ void select_kernel(const float* __restrict__ x, const float* __restrict__ keys) {
    const int row = blockIdx.x;
    __shared__ float xs[KD];
    __shared__ int cidx[CAND];
    __shared__ unsigned long long ck[CAND];
    const int tid = threadIdx.x, wid = tid >> 5, lane = tid & 31;

    *(float4*)&xs[tid * 4] = *(const float4*)(x + (size_t)row * KD + tid * 4);

    if (wid == 0) {
        unsigned a[16];
        #pragma unroll
        for (int q = 0; q < 16; q++) a[q] = 0xFFFFFFFFu;
        uint4 v = *(const uint4*)(g_tilecand + ((size_t)row * NTILE + lane) * 4);
        insert16(a, v.x); insert16(a, v.y); insert16(a, v.z); insert16(a, v.w);
        #pragma unroll
        for (int off = 16; off; off >>= 1) {
            unsigned b[16];
            #pragma unroll
            for (int q = 0; q < 16; q++) b[q] = __shfl_xor_sync(0xffffffffu, a[q], off);
            merge16(a, b);
        }
        if (lane < 16) cidx[lane] = (int)(a[lane] & 0xFFFu);
    }
    __syncthreads();

    for (int c = wid; c < CAND; c += 4) {
        const int idx = cidx[c];
        const float* kr = keys + (size_t)idx * KD;
        float sum = 0.f;
        #pragma unroll
        for (int j = 0; j < 16; j++) sum = fmaf(xs[lane + 32 * j], kr[lane + 32 * j], sum);
        #pragma unroll
        for (int o = 16; o; o >>= 1) sum += __shfl_xor_sync(0xffffffffu, sum, o);
        if (lane == 0) {
            float sc = sum * g_invk[idx];
            ck[c] = ((unsigned long long)fmap(sc) << 32) | (unsigned)idx;
        }
    }
    __syncthreads();
    if (tid == 0) {
        #pragma unroll
        for (int q = 0; q < TOPK; q++) {
            unsigned long long best = ~0ull; int bi = 0;
            #pragma unroll
            for (int c = 0; c < CAND; c++) if (ck[c] < best) { best = ck[c]; bi = c; }
            ck[bi] = ~0ull;
            int idx = (int)(best & 0xffffffffu);
            g_topidx[row * TOPK + q] = idx;
            atomicAdd(&g_binCount[idx], 1);
        }
    }
}

// ---------------- kernel 4: exclusive scan over 4096 bins (1 block) -------
__global__ void scan_kernel() {
    __shared__ int ssum[1024];
    const int t = threadIdx.x;
    int4 v = ((const int4*)g_binCount)[t];
    int s = v.x + v.y + v.z + v.w;
    ssum[t] = s;
    __syncthreads();
    for (int off = 1; off < 1024; off <<= 1) {
        int other = 0;
        if (t >= off) other = ssum[t - off];
        __syncthreads();
        if (t >= off) ssum[t] += other;
        __syncthreads();
    }
    int excl = ssum[t] - s;
    int4 st;
    st.x = excl;
    st.y = excl + v.x;
    st.z = excl + v.x + v.y;
    st.w = excl + v.x + v.y + v.z;
    ((int4*)g_binStart)[t] = st;
}

// ---------------- kernel 5: scatter work items by index -------------------
__global__ void scatter_kernel() {
    int w = blockIdx.x * 256 + threadIdx.x;
    int idx = g_topidx[w];
    int pos = atomicAdd(&g_binStart[idx], 1);
    g_order[pos] = w;
}

// ---------------- kernel 6: index-sorted gather ---------------------------
__global__ void gather_kernel(const float* __restrict__ pv, float* __restrict__ out) {
    const int w = g_order[blockIdx.x];
    const int idx = g_topidx[w];
    const float4* src = (const float4*)(pv + (size_t)idx * ROW_ELEMS);
    float4* dst = (float4*)(out + (size_t)w * ROW_ELEMS);
    #pragma unroll 8
    for (int i = threadIdx.x; i < ROW_ELEMS / 4; i += 256)
        __stcs(dst + i, __ldg(src + i));
}

// ---------------- launcher ----------------
extern "C" void kernel_launch(void* const* d_in, const int* in_sizes, int n_in,
                              void* d_out, int out_size) {
    const float* x    = (const float*)d_in[0];   // (4096, 512)
    const float* keys = (const float*)d_in[1];   // (4096, 512)
    const float* pv   = (const float*)d_in[2];   // (4096, 16, 512)
    float* out = (float*)d_out;

    convert_all_kernel<<<1024 + NP / 8 + 16, 256>>>(x, keys);
    coarse_gemm<<<dim3(NP / BN, NB / BM), 256>>>();
    select_kernel<<<NB, 128>>>(x, keys);
    scan_kernel<<<1, 1024>>>();
    scatter_kernel<<<NWORK / 256, 256>>>();
    gather_kernel<<<NWORK, 256>>>(pv, out);
}